// round 1
// baseline (speedup 1.0000x reference)
#include <cuda_runtime.h>
#include <cuda_bf16.h>
#include <math.h>

#define T_ 16
#define HW_ 1024
#define M_ 256
#define D_ 768
#define H_ 8
#define HD_ 96
#define SCALE_F 0.1020620726159658f  /* 1/sqrt(96) */

// ---------------- scratch (static device globals; no allocation) ----------------
__device__ float g_bias[(size_t)T_ * M_ * HW_];          // [T,M,HW]
__device__ float g_fp  [(size_t)T_ * HW_ * D_];          // featplus / Q2
__device__ float g_k   [(size_t)T_ * HW_ * D_];          // K / upd
__device__ float g_v   [(size_t)T_ * HW_ * D_];          // V
__device__ float g_q   [(size_t)T_ * M_  * D_];          // Q / K2
__device__ float g_sh  [(size_t)T_ * M_  * D_];          // sampled-heads / V2
__device__ float g_samp[(size_t)T_ * M_  * D_];          // sampled
__device__ float g_attn[(size_t)T_ * H_ * M_ * HW_];     // attention probs (both phases)

// ---------------- bias: -||track - fpos||^2 / (2*sigma^2), sigma=0.5 -> -2*d2 ----
__global__ __launch_bounds__(256) void bias_kernel(
    const float* __restrict__ tracks, const float* __restrict__ fpos,
    float* __restrict__ bias)
{
    int tm = blockIdx.x;                 // t*M + m
    float px = tracks[2 * tm + 0];
    float py = tracks[2 * tm + 1];
    float* brow = bias + (size_t)tm * HW_;
    for (int n = threadIdx.x; n < HW_; n += 256) {
        float dx = px - fpos[2 * n + 0];
        float dy = py - fpos[2 * n + 1];
        brow[n] = -2.0f * (dx * dx + dy * dy);
    }
}

// ---------------- elementwise add ----------------
__global__ __launch_bounds__(256) void add_kernel(
    const float* __restrict__ a, const float* __restrict__ b,
    float* __restrict__ c, int n)
{
    int i = blockIdx.x * 256 + threadIdx.x;
    if (i < n) c[i] = a[i] + b[i];
}

// ---------------- generic NT GEMM: C[R,J] = A[R,K] @ W[J,K]^T (+ addsrc) --------
// grid: (J/64, R/64); block 256; 64x64 tile, k-step 16, 4x4 per thread.
__global__ __launch_bounds__(256) void gemm_nt(
    const float* __restrict__ A, const float* __restrict__ W,
    const float* __restrict__ addsrc, float* __restrict__ C, int K)
{
    __shared__ float As[64][17];
    __shared__ float Ws[64][17];
    const int bm = blockIdx.y * 64;
    const int bn = blockIdx.x * 64;
    const int tid = threadIdx.x;
    const int ty = tid >> 4, tx = tid & 15;
    const int J = gridDim.x * 64;
    float acc[4][4] = {};

    for (int k0 = 0; k0 < K; k0 += 16) {
#pragma unroll
        for (int i = 0; i < 4; i++) {
            int idx = tid + i * 256;
            int r = idx >> 4, c = idx & 15;
            As[r][c] = A[(size_t)(bm + r) * K + k0 + c];
            Ws[r][c] = W[(size_t)(bn + r) * K + k0 + c];
        }
        __syncthreads();
#pragma unroll
        for (int k = 0; k < 16; k++) {
            float a[4], b[4];
#pragma unroll
            for (int i = 0; i < 4; i++) a[i] = As[ty * 4 + i][k];
#pragma unroll
            for (int j = 0; j < 4; j++) b[j] = Ws[tx * 4 + j][k];
#pragma unroll
            for (int i = 0; i < 4; i++)
#pragma unroll
                for (int j = 0; j < 4; j++)
                    acc[i][j] += a[i] * b[j];
        }
        __syncthreads();
    }
#pragma unroll
    for (int i = 0; i < 4; i++)
#pragma unroll
        for (int j = 0; j < 4; j++) {
            size_t o = (size_t)(bm + ty * 4 + i) * J + bn + tx * 4 + j;
            float vv = acc[i][j];
            if (addsrc) vv += addsrc[o];
            C[o] = vv;
        }
}

// ---------------- LayerNorm (row length 768), in-place, gain, eps=1e-6 ----------
__global__ __launch_bounds__(256) void layernorm(float* X, const float* __restrict__ g)
{
    float* row = X + (size_t)blockIdx.x * D_;
    int tid = threadIdx.x;
    float v0 = row[tid], v1 = row[tid + 256], v2 = row[tid + 512];
    __shared__ float red[256];
    red[tid] = v0 + v1 + v2;
    __syncthreads();
    for (int s = 128; s > 0; s >>= 1) { if (tid < s) red[tid] += red[tid + s]; __syncthreads(); }
    float mean = red[0] * (1.0f / 768.0f);
    __syncthreads();
    float d0 = v0 - mean, d1 = v1 - mean, d2 = v2 - mean;
    red[tid] = d0 * d0 + d1 * d1 + d2 * d2;
    __syncthreads();
    for (int s = 128; s > 0; s >>= 1) { if (tid < s) red[tid] += red[tid + s]; __syncthreads(); }
    float inv = rsqrtf(red[0] * (1.0f / 768.0f) + 1e-6f);
    row[tid]       = d0 * inv * g[tid];
    row[tid + 256] = d1 * inv * g[tid + 256];
    row[tid + 512] = d2 * inv * g[tid + 512];
}

// ---------------- attention scores: S[th, q, k] = Qh.Kh * SCALE + bias ----------
// Q rows = Mq queries (row stride D_, head offset h*HD_), K rows = Nk keys.
// transposed=0: bias[t][q][k] (sampling). transposed=1: bias[t][k][q] (splatting).
// grid: (Nk/64, Mq/64, T_*H_)
__global__ __launch_bounds__(256) void attn_scores(
    const float* __restrict__ Q, const float* __restrict__ Kp,
    const float* __restrict__ bias, float* __restrict__ S,
    int Mq, int Nk, int transposed)
{
    int th = blockIdx.z;
    int t = th >> 3, h = th & 7;
    const float* Qb = Q + (size_t)t * Mq * D_ + h * HD_;
    const float* Kb = Kp + (size_t)t * Nk * D_ + h * HD_;
    __shared__ float As[64][17];
    __shared__ float Ws[64][17];
    const int bm = blockIdx.y * 64;
    const int bn = blockIdx.x * 64;
    const int tid = threadIdx.x;
    const int ty = tid >> 4, tx = tid & 15;
    float acc[4][4] = {};

    for (int k0 = 0; k0 < HD_; k0 += 16) {
#pragma unroll
        for (int i = 0; i < 4; i++) {
            int idx = tid + i * 256;
            int r = idx >> 4, c = idx & 15;
            As[r][c] = Qb[(size_t)(bm + r) * D_ + k0 + c];
            Ws[r][c] = Kb[(size_t)(bn + r) * D_ + k0 + c];
        }
        __syncthreads();
#pragma unroll
        for (int k = 0; k < 16; k++) {
            float a[4], b[4];
#pragma unroll
            for (int i = 0; i < 4; i++) a[i] = As[ty * 4 + i][k];
#pragma unroll
            for (int j = 0; j < 4; j++) b[j] = Ws[tx * 4 + j][k];
#pragma unroll
            for (int i = 0; i < 4; i++)
#pragma unroll
                for (int j = 0; j < 4; j++)
                    acc[i][j] += a[i] * b[j];
        }
        __syncthreads();
    }
    const size_t bbase = (size_t)t * M_ * HW_;
#pragma unroll
    for (int i = 0; i < 4; i++) {
        int ri = bm + ty * 4 + i;
#pragma unroll
        for (int j = 0; j < 4; j++) {
            int cj = bn + tx * 4 + j;
            float bv = transposed ? bias[bbase + (size_t)cj * HW_ + ri]
                                  : bias[bbase + (size_t)ri * HW_ + cj];
            S[((size_t)th * Mq + ri) * Nk + cj] = acc[i][j] * SCALE_F + bv;
        }
    }
}

// ---------------- row softmax (in place), row length L ----------------
__global__ __launch_bounds__(256) void softmax_rows(float* __restrict__ S, int L)
{
    float* row = S + (size_t)blockIdx.x * L;
    __shared__ float red[256];
    int tid = threadIdx.x;
    float mx = -1e30f;
    for (int j = tid; j < L; j += 256) mx = fmaxf(mx, row[j]);
    red[tid] = mx;
    __syncthreads();
    for (int s = 128; s > 0; s >>= 1) { if (tid < s) red[tid] = fmaxf(red[tid], red[tid + s]); __syncthreads(); }
    mx = red[0];
    __syncthreads();
    float sum = 0.0f;
    for (int j = tid; j < L; j += 256) { float e = __expf(row[j] - mx); row[j] = e; sum += e; }
    red[tid] = sum;
    __syncthreads();
    for (int s = 128; s > 0; s >>= 1) { if (tid < s) red[tid] += red[tid + s]; __syncthreads(); }
    float inv = 1.0f / red[0];
    __syncthreads();
    for (int j = tid; j < L; j += 256) row[j] *= inv;
}

// ---------------- AV: O[t, q, h*96+d] = sum_k S[th,q,k] * V[t,k,h*96+d] ---------
// grid: (1, Mq/64, T_*H_); block 256; tile 64(q) x 96(d), k-step 32; 4x6 per thread.
__global__ __launch_bounds__(256) void attn_av(
    const float* __restrict__ S, const float* __restrict__ V,
    float* __restrict__ O, int Mq, int Kn)
{
    int th = blockIdx.z;
    int t = th >> 3, h = th & 7;
    const float* Sb = S + (size_t)th * Mq * Kn;
    const float* Vb = V + (size_t)t * Kn * D_ + h * HD_;
    float* Ob = O + (size_t)t * Mq * D_ + h * HD_;
    const int bm = blockIdx.y * 64;
    __shared__ float As[64][33];
    __shared__ float Vs[32][97];
    const int tid = threadIdx.x;
    const int ty = tid >> 4, tx = tid & 15;
    float acc[4][6] = {};

    for (int k0 = 0; k0 < Kn; k0 += 32) {
#pragma unroll
        for (int i = 0; i < 8; i++) {
            int idx = tid + i * 256;
            int r = idx >> 5, c = idx & 31;
            As[r][c] = Sb[(size_t)(bm + r) * Kn + k0 + c];
        }
#pragma unroll
        for (int i = 0; i < 12; i++) {
            int idx = tid + i * 256;
            int r = idx / 96, c = idx % 96;
            Vs[r][c] = Vb[(size_t)(k0 + r) * D_ + c];
        }
        __syncthreads();
#pragma unroll
        for (int k = 0; k < 32; k++) {
            float a[4], b[6];
#pragma unroll
            for (int i = 0; i < 4; i++) a[i] = As[ty * 4 + i][k];
#pragma unroll
            for (int j = 0; j < 6; j++) b[j] = Vs[k][tx * 6 + j];
#pragma unroll
            for (int i = 0; i < 4; i++)
#pragma unroll
                for (int j = 0; j < 6; j++)
                    acc[i][j] += a[i] * b[j];
        }
        __syncthreads();
    }
#pragma unroll
    for (int i = 0; i < 4; i++)
#pragma unroll
        for (int j = 0; j < 6; j++)
            Ob[(size_t)(bm + ty * 4 + i) * D_ + tx * 6 + j] = acc[i][j];
}

// =================================================================================
extern "C" void kernel_launch(void* const* d_in, const int* in_sizes, int n_in,
                              void* d_out, int out_size)
{
    const float* features = (const float*)d_in[0];
    const float* tracks   = (const float*)d_in[1];
    const float* fpos     = (const float*)d_in[2];
    const float* tpe      = (const float*)d_in[3];
    const float* fpe      = (const float*)d_in[4];
    const float* Wq_s  = (const float*)d_in[5];
    const float* Wk_s  = (const float*)d_in[6];
    const float* Wv_s  = (const float*)d_in[7];
    const float* qg_s  = (const float*)d_in[8];
    const float* kg_s  = (const float*)d_in[9];
    const float* Wo_s  = (const float*)d_in[10];
    const float* Wq_p  = (const float*)d_in[11];
    const float* Wk_p  = (const float*)d_in[12];
    const float* Wv_p  = (const float*)d_in[13];
    const float* qg_p  = (const float*)d_in[14];
    const float* kg_p  = (const float*)d_in[15];
    const float* Wout_p = (const float*)d_in[16];
    float* out = (float*)d_out;

    float *bias, *fp, *kb, *vb, *qb, *sh, *samp, *attn;
    cudaGetSymbolAddress((void**)&bias, g_bias);
    cudaGetSymbolAddress((void**)&fp,   g_fp);
    cudaGetSymbolAddress((void**)&kb,   g_k);
    cudaGetSymbolAddress((void**)&vb,   g_v);
    cudaGetSymbolAddress((void**)&qb,   g_q);
    cudaGetSymbolAddress((void**)&sh,   g_sh);
    cudaGetSymbolAddress((void**)&samp, g_samp);
    cudaGetSymbolAddress((void**)&attn, g_attn);

    const int NBIG = T_ * HW_ * D_;   // 12,582,912

    // bias
    bias_kernel<<<T_ * M_, 256>>>(tracks, fpos, bias);
    // featplus = features + fpe
    add_kernel<<<(NBIG + 255) / 256, 256>>>(features, fpe, fp, NBIG);

    dim3 gBig(D_ / 64, (T_ * HW_) / 64);   // (12, 256)
    dim3 gSm (D_ / 64, (T_ * M_) / 64);    // (12, 64)

    // ---- sampling ----
    gemm_nt<<<gBig, 256>>>(fp, Wk_s, nullptr, kb, D_);        // K
    layernorm<<<T_ * HW_, 256>>>(kb, kg_s);
    gemm_nt<<<gBig, 256>>>(features, Wv_s, nullptr, vb, D_);  // V
    gemm_nt<<<gSm, 256>>>(tpe, Wq_s, nullptr, qb, D_);        // Q
    layernorm<<<T_ * M_, 256>>>(qb, qg_s);

    dim3 gs1(HW_ / 64, M_ / 64, T_ * H_);
    attn_scores<<<gs1, 256>>>(qb, kb, bias, attn, M_, HW_, 0);
    softmax_rows<<<T_ * H_ * M_, 256>>>(attn, HW_);
    dim3 ga1(1, M_ / 64, T_ * H_);
    attn_av<<<ga1, 256>>>(attn, vb, sh, M_, HW_);

    gemm_nt<<<gSm, 256>>>(sh, Wo_s, nullptr, samp, D_);       // sampled

    // ---- splatting ----
    gemm_nt<<<gBig, 256>>>(fpe, Wq_p, nullptr, fp, D_);       // Q2
    layernorm<<<T_ * HW_, 256>>>(fp, qg_p);
    gemm_nt<<<gSm, 256>>>(tpe, Wk_p, nullptr, qb, D_);        // K2
    layernorm<<<T_ * M_, 256>>>(qb, kg_p);
    gemm_nt<<<gSm, 256>>>(samp, Wv_p, nullptr, sh, D_);       // V2

    dim3 gs2(M_ / 64, HW_ / 64, T_ * H_);
    attn_scores<<<gs2, 256>>>(fp, qb, bias, attn, HW_, M_, 1);
    softmax_rows<<<T_ * H_ * HW_, 256>>>(attn, M_);
    dim3 ga2(1, HW_ / 64, T_ * H_);
    attn_av<<<ga2, 256>>>(attn, sh, kb, HW_, M_);

    // out = features + updH @ Wout_p^T
    gemm_nt<<<gBig, 256>>>(kb, Wout_p, features, out, D_);
}

// round 2
// speedup vs baseline: 2.9482x; 2.9482x over previous
#include <cuda_runtime.h>
#include <cuda_bf16.h>
#include <math.h>

#define T_ 16
#define HW_ 1024
#define M_ 256
#define D_ 768
#define H_ 8
#define HD_ 96
#define SCALE_F 0.1020620726159658f  /* 1/sqrt(96) */

// ---------------- scratch (static device globals; no allocation) ----------------
__device__ float g_bias[(size_t)T_ * M_ * HW_];          // [T,M,HW]
__device__ float g_fp  [(size_t)T_ * HW_ * D_];          // featplus / Q2
__device__ float g_k   [(size_t)T_ * HW_ * D_];          // K / upd
__device__ float g_v   [(size_t)T_ * HW_ * D_];          // V
__device__ float g_q   [(size_t)T_ * M_  * D_];          // Q / K2
__device__ float g_sh  [(size_t)T_ * M_  * D_];          // sampled-heads / V2
__device__ float g_samp[(size_t)T_ * M_  * D_];          // sampled
__device__ float g_attn[(size_t)T_ * H_ * M_ * HW_];     // attention probs (both phases)

// ---------------- helpers ----------------
__device__ __forceinline__ float f2tf(float x) {
    unsigned r;
    asm("cvt.rna.tf32.f32 %0, %1;" : "=r"(r) : "f"(x));
    return __uint_as_float(r);
}

__device__ __forceinline__ void mma_tf32(float* c, const unsigned* a, unsigned b0, unsigned b1) {
    asm volatile(
        "mma.sync.aligned.m16n8k8.row.col.f32.tf32.tf32.f32 "
        "{%0,%1,%2,%3}, {%4,%5,%6,%7}, {%8,%9}, {%0,%1,%2,%3};\n"
        : "+f"(c[0]), "+f"(c[1]), "+f"(c[2]), "+f"(c[3])
        : "r"(a[0]), "r"(a[1]), "r"(a[2]), "r"(a[3]), "r"(b0), "r"(b1));
}

// swizzled index into [rows][32] tile: k in [0,32)
__device__ __forceinline__ int swz(int row, int k) {
    return row * 32 + ((((k >> 2) ^ (row & 7)) << 2) | (k & 3));
}

// ---------------- bias ----------------
__global__ __launch_bounds__(256) void bias_kernel(
    const float* __restrict__ tracks, const float* __restrict__ fpos,
    float* __restrict__ bias)
{
    int tm = blockIdx.x;
    float px = tracks[2 * tm + 0];
    float py = tracks[2 * tm + 1];
    float* brow = bias + (size_t)tm * HW_;
    for (int n = threadIdx.x; n < HW_; n += 256) {
        float dx = px - fpos[2 * n + 0];
        float dy = py - fpos[2 * n + 1];
        brow[n] = -2.0f * (dx * dx + dy * dy);
    }
}

__global__ __launch_bounds__(256) void add_kernel(
    const float* __restrict__ a, const float* __restrict__ b,
    float* __restrict__ c, int n)
{
    int i = blockIdx.x * 256 + threadIdx.x;
    if (i < n) c[i] = a[i] + b[i];
}

// ---------------- dense NT GEMM (tf32 tensor core) ----------------
// C[R,N] = A[R,K] @ W[N,K]^T (+addsrc). 128x128 tile, BK=32, 256 thr (8 warps 4x2).
__global__ __launch_bounds__(256) void gemm_tf32(
    const float* __restrict__ A, const float* __restrict__ W,
    const float* __restrict__ addsrc, float* __restrict__ C, int K)
{
    __shared__ float As[128 * 32];
    __shared__ float Ws[128 * 32];
    const int tid = threadIdx.x;
    const int lane = tid & 31, warp = tid >> 5;
    const int wm = warp & 3, wn = warp >> 2;
    const int bm = blockIdx.y * 128, bn = blockIdx.x * 128;
    const int N = gridDim.x * 128;
    const int gq = lane >> 2, tg = lane & 3;

    float c[2][8][4];
#pragma unroll
    for (int i = 0; i < 2; i++)
#pragma unroll
        for (int j = 0; j < 8; j++)
#pragma unroll
            for (int l = 0; l < 4; l++) c[i][j][l] = 0.0f;

    float4 ra[4], rw[4];
    const int iters = K / 32;

    // prefetch iter 0
#pragma unroll
    for (int i = 0; i < 4; i++) {
        int v = tid + i * 256; int r = v >> 3, gg = v & 7;
        ra[i] = *(const float4*)(A + (size_t)(bm + r) * K + gg * 4);
        rw[i] = *(const float4*)(W + (size_t)(bn + r) * K + gg * 4);
    }

    for (int it = 0; it < iters; ++it) {
        // STS with tf32 rounding + xor swizzle
#pragma unroll
        for (int i = 0; i < 4; i++) {
            int v = tid + i * 256; int r = v >> 3, gg = v & 7;
            int off = r * 32 + (((gg ^ (r & 7)) << 2));
            As[off + 0] = f2tf(ra[i].x); As[off + 1] = f2tf(ra[i].y);
            As[off + 2] = f2tf(ra[i].z); As[off + 3] = f2tf(ra[i].w);
            Ws[off + 0] = f2tf(rw[i].x); Ws[off + 1] = f2tf(rw[i].y);
            Ws[off + 2] = f2tf(rw[i].z); Ws[off + 3] = f2tf(rw[i].w);
        }
        __syncthreads();
        if (it + 1 < iters) {
            int k0 = (it + 1) * 32;
#pragma unroll
            for (int i = 0; i < 4; i++) {
                int v = tid + i * 256; int r = v >> 3, gg = v & 7;
                ra[i] = *(const float4*)(A + (size_t)(bm + r) * K + k0 + gg * 4);
                rw[i] = *(const float4*)(W + (size_t)(bn + r) * K + k0 + gg * 4);
            }
        }
#pragma unroll
        for (int kk = 0; kk < 32; kk += 8) {
            unsigned a[2][4], b[8][2];
#pragma unroll
            for (int mt = 0; mt < 2; mt++) {
                int row = wm * 32 + mt * 16 + gq;
                a[mt][0] = __float_as_uint(As[swz(row,     kk + tg)]);
                a[mt][1] = __float_as_uint(As[swz(row + 8, kk + tg)]);
                a[mt][2] = __float_as_uint(As[swz(row,     kk + 4 + tg)]);
                a[mt][3] = __float_as_uint(As[swz(row + 8, kk + 4 + tg)]);
            }
#pragma unroll
            for (int nt = 0; nt < 8; nt++) {
                int nr = wn * 64 + nt * 8 + gq;
                b[nt][0] = __float_as_uint(Ws[swz(nr, kk + tg)]);
                b[nt][1] = __float_as_uint(Ws[swz(nr, kk + 4 + tg)]);
            }
#pragma unroll
            for (int mt = 0; mt < 2; mt++)
#pragma unroll
                for (int nt = 0; nt < 8; nt++)
                    mma_tf32(c[mt][nt], a[mt], b[nt][0], b[nt][1]);
        }
        __syncthreads();
    }

    // epilogue
#pragma unroll
    for (int mt = 0; mt < 2; mt++) {
        int m0 = bm + wm * 32 + mt * 16 + gq;
#pragma unroll
        for (int nt = 0; nt < 8; nt++) {
            int n0 = bn + wn * 64 + nt * 8 + 2 * tg;
            size_t o0 = (size_t)m0 * N + n0;
            size_t o1 = (size_t)(m0 + 8) * N + n0;
            float2 v0 = make_float2(c[mt][nt][0], c[mt][nt][1]);
            float2 v1 = make_float2(c[mt][nt][2], c[mt][nt][3]);
            if (addsrc) {
                float2 s0 = *(const float2*)(addsrc + o0);
                float2 s1 = *(const float2*)(addsrc + o1);
                v0.x += s0.x; v0.y += s0.y; v1.x += s1.x; v1.y += s1.y;
            }
            *(float2*)(C + o0) = v0;
            *(float2*)(C + o1) = v1;
        }
    }
}

// ---------------- LayerNorm ----------------
__global__ __launch_bounds__(256) void layernorm(float* X, const float* __restrict__ g)
{
    float* row = X + (size_t)blockIdx.x * D_;
    int tid = threadIdx.x;
    float v0 = row[tid], v1 = row[tid + 256], v2 = row[tid + 512];
    __shared__ float red[256];
    red[tid] = v0 + v1 + v2;
    __syncthreads();
    for (int s = 128; s > 0; s >>= 1) { if (tid < s) red[tid] += red[tid + s]; __syncthreads(); }
    float mean = red[0] * (1.0f / 768.0f);
    __syncthreads();
    float d0 = v0 - mean, d1 = v1 - mean, d2 = v2 - mean;
    red[tid] = d0 * d0 + d1 * d1 + d2 * d2;
    __syncthreads();
    for (int s = 128; s > 0; s >>= 1) { if (tid < s) red[tid] += red[tid + s]; __syncthreads(); }
    float inv = rsqrtf(red[0] * (1.0f / 768.0f) + 1e-6f);
    row[tid]       = d0 * inv * g[tid];
    row[tid + 256] = d1 * inv * g[tid + 256];
    row[tid + 512] = d2 * inv * g[tid + 512];
}

// ---------------- attention scores (tf32): S = Q.K^T * SCALE + bias ----------------
// 64x64 tile, BK=32, 256 thr (8 warps, 4m x 2n, warp tile 16x32).
// grid: (Nk/64, Mq/64, T_*H_)
__global__ __launch_bounds__(256) void scores_tf32(
    const float* __restrict__ Q, const float* __restrict__ Kp,
    const float* __restrict__ bias, float* __restrict__ S,
    int Mq, int Nk, int transposed)
{
    __shared__ float As[64 * 32];
    __shared__ float Bs[64 * 32];
    const int tid = threadIdx.x;
    const int lane = tid & 31, warp = tid >> 5;
    const int wm = warp & 3, wn = warp >> 2;
    const int bm = blockIdx.y * 64, bn = blockIdx.x * 64;
    const int gq = lane >> 2, tg = lane & 3;
    const int zz = blockIdx.z;
    const int t = zz >> 3, h = zz & 7;
    const float* Qb = Q + (size_t)t * Mq * D_ + h * HD_;
    const float* Kb = Kp + (size_t)t * Nk * D_ + h * HD_;

    float c[4][4];
#pragma unroll
    for (int j = 0; j < 4; j++)
#pragma unroll
        for (int l = 0; l < 4; l++) c[j][l] = 0.0f;

    for (int it = 0; it < 3; ++it) {   // K = 96
        int k0 = it * 32;
#pragma unroll
        for (int i = 0; i < 2; i++) {
            int v = tid + i * 256; int r = v >> 3, gg = v & 7;
            float4 qa = *(const float4*)(Qb + (size_t)(bm + r) * D_ + k0 + gg * 4);
            float4 kb = *(const float4*)(Kb + (size_t)(bn + r) * D_ + k0 + gg * 4);
            int off = r * 32 + (((gg ^ (r & 7)) << 2));
            As[off + 0] = f2tf(qa.x); As[off + 1] = f2tf(qa.y);
            As[off + 2] = f2tf(qa.z); As[off + 3] = f2tf(qa.w);
            Bs[off + 0] = f2tf(kb.x); Bs[off + 1] = f2tf(kb.y);
            Bs[off + 2] = f2tf(kb.z); Bs[off + 3] = f2tf(kb.w);
        }
        __syncthreads();
#pragma unroll
        for (int kk = 0; kk < 32; kk += 8) {
            unsigned a[4], b[4][2];
            int row = wm * 16 + gq;
            a[0] = __float_as_uint(As[swz(row,     kk + tg)]);
            a[1] = __float_as_uint(As[swz(row + 8, kk + tg)]);
            a[2] = __float_as_uint(As[swz(row,     kk + 4 + tg)]);
            a[3] = __float_as_uint(As[swz(row + 8, kk + 4 + tg)]);
#pragma unroll
            for (int nt = 0; nt < 4; nt++) {
                int nr = wn * 32 + nt * 8 + gq;
                b[nt][0] = __float_as_uint(Bs[swz(nr, kk + tg)]);
                b[nt][1] = __float_as_uint(Bs[swz(nr, kk + 4 + tg)]);
            }
#pragma unroll
            for (int nt = 0; nt < 4; nt++)
                mma_tf32(c[nt], a, b[nt][0], b[nt][1]);
        }
        __syncthreads();
    }

    const size_t bbase = (size_t)t * M_ * HW_;
#pragma unroll
    for (int nt = 0; nt < 4; nt++) {
        int n0 = bn + wn * 32 + nt * 8 + 2 * tg;
#pragma unroll
        for (int half = 0; half < 2; half++) {
            int m = bm + wm * 16 + gq + half * 8;
            float s0 = c[nt][half * 2 + 0] * SCALE_F;
            float s1 = c[nt][half * 2 + 1] * SCALE_F;
            if (transposed) {
                s0 += bias[bbase + (size_t)n0 * HW_ + m];
                s1 += bias[bbase + (size_t)(n0 + 1) * HW_ + m];
            } else {
                s0 += bias[bbase + (size_t)m * HW_ + n0];
                s1 += bias[bbase + (size_t)m * HW_ + n0 + 1];
            }
            S[((size_t)zz * Mq + m) * Nk + n0]     = s0;
            S[((size_t)zz * Mq + m) * Nk + n0 + 1] = s1;
        }
    }
}

// ---------------- row softmax ----------------
__global__ __launch_bounds__(256) void softmax_rows(float* __restrict__ S, int L)
{
    float* row = S + (size_t)blockIdx.x * L;
    __shared__ float red[256];
    int tid = threadIdx.x;
    float mx = -1e30f;
    for (int j = tid; j < L; j += 256) mx = fmaxf(mx, row[j]);
    red[tid] = mx;
    __syncthreads();
    for (int s = 128; s > 0; s >>= 1) { if (tid < s) red[tid] = fmaxf(red[tid], red[tid + s]); __syncthreads(); }
    mx = red[0];
    __syncthreads();
    float sum = 0.0f;
    for (int j = tid; j < L; j += 256) { float e = __expf(row[j] - mx); row[j] = e; sum += e; }
    red[tid] = sum;
    __syncthreads();
    for (int s = 128; s > 0; s >>= 1) { if (tid < s) red[tid] += red[tid + s]; __syncthreads(); }
    float inv = 1.0f / red[0];
    __syncthreads();
    for (int j = tid; j < L; j += 256) row[j] *= inv;
}

// ---------------- AV (tf32): O[t,m,h*96+d] = sum_k S[z,m,k] * V[t,k,h*96+d] --------
// 64(m) x 96(n) tile, BK=32, 128 thr (4 warps along m, warp tile 16x96).
// grid: (1, Mq/64, T_*H_)
__global__ __launch_bounds__(128) void av_tf32(
    const float* __restrict__ S, const float* __restrict__ V,
    float* __restrict__ O, int Mq, int Kn)
{
    __shared__ float As[64 * 32];
    __shared__ float Vs[32 * 104];
    const int tid = threadIdx.x;
    const int lane = tid & 31, warp = tid >> 5;
    const int bm = blockIdx.y * 64;
    const int gq = lane >> 2, tg = lane & 3;
    const int zz = blockIdx.z;
    const int t = zz >> 3, h = zz & 7;
    const float* Sb = S + (size_t)zz * Mq * Kn;
    const float* Vb = V + (size_t)t * Kn * D_ + h * HD_;
    float* Ob = O + (size_t)t * Mq * D_ + h * HD_;

    float c[12][4];
#pragma unroll
    for (int j = 0; j < 12; j++)
#pragma unroll
        for (int l = 0; l < 4; l++) c[j][l] = 0.0f;

    const int iters = Kn / 32;
    for (int it = 0; it < iters; ++it) {
        int k0 = it * 32;
        // stage S tile 64x32 (swizzled)
#pragma unroll
        for (int i = 0; i < 4; i++) {
            int v = tid + i * 128; int r = v >> 3, gg = v & 7;
            float4 sa = *(const float4*)(Sb + (size_t)(bm + r) * Kn + k0 + gg * 4);
            int off = r * 32 + (((gg ^ (r & 7)) << 2));
            As[off + 0] = f2tf(sa.x); As[off + 1] = f2tf(sa.y);
            As[off + 2] = f2tf(sa.z); As[off + 3] = f2tf(sa.w);
        }
        // stage V tile 32x96 (k-major, pad 104)
#pragma unroll
        for (int i = 0; i < 6; i++) {
            int v = tid + i * 128; int r = v / 24, c4 = v % 24;
            float4 va = *(const float4*)(Vb + (size_t)(k0 + r) * D_ + c4 * 4);
            int off = r * 104 + c4 * 4;
            Vs[off + 0] = f2tf(va.x); Vs[off + 1] = f2tf(va.y);
            Vs[off + 2] = f2tf(va.z); Vs[off + 3] = f2tf(va.w);
        }
        __syncthreads();
#pragma unroll
        for (int kk = 0; kk < 32; kk += 8) {
            unsigned a[4];
            int row = warp * 16 + gq;
            a[0] = __float_as_uint(As[swz(row,     kk + tg)]);
            a[1] = __float_as_uint(As[swz(row + 8, kk + tg)]);
            a[2] = __float_as_uint(As[swz(row,     kk + 4 + tg)]);
            a[3] = __float_as_uint(As[swz(row + 8, kk + 4 + tg)]);
#pragma unroll
            for (int nt = 0; nt < 12; nt++) {
                int n = nt * 8 + gq;
                unsigned b0 = __float_as_uint(Vs[(kk + tg) * 104 + n]);
                unsigned b1 = __float_as_uint(Vs[(kk + 4 + tg) * 104 + n]);
                mma_tf32(c[nt], a, b0, b1);
            }
        }
        __syncthreads();
    }

#pragma unroll
    for (int nt = 0; nt < 12; nt++) {
        int n0 = nt * 8 + 2 * tg;
        int m0 = bm + warp * 16 + gq;
        *(float2*)(Ob + (size_t)m0 * D_ + n0)       = make_float2(c[nt][0], c[nt][1]);
        *(float2*)(Ob + (size_t)(m0 + 8) * D_ + n0) = make_float2(c[nt][2], c[nt][3]);
    }
}

// =================================================================================
extern "C" void kernel_launch(void* const* d_in, const int* in_sizes, int n_in,
                              void* d_out, int out_size)
{
    const float* features = (const float*)d_in[0];
    const float* tracks   = (const float*)d_in[1];
    const float* fpos     = (const float*)d_in[2];
    const float* tpe      = (const float*)d_in[3];
    const float* fpe      = (const float*)d_in[4];
    const float* Wq_s  = (const float*)d_in[5];
    const float* Wk_s  = (const float*)d_in[6];
    const float* Wv_s  = (const float*)d_in[7];
    const float* qg_s  = (const float*)d_in[8];
    const float* kg_s  = (const float*)d_in[9];
    const float* Wo_s  = (const float*)d_in[10];
    const float* Wq_p  = (const float*)d_in[11];
    const float* Wk_p  = (const float*)d_in[12];
    const float* Wv_p  = (const float*)d_in[13];
    const float* qg_p  = (const float*)d_in[14];
    const float* kg_p  = (const float*)d_in[15];
    const float* Wout_p = (const float*)d_in[16];
    float* out = (float*)d_out;

    float *bias, *fp, *kb, *vb, *qb, *sh, *samp, *attn;
    cudaGetSymbolAddress((void**)&bias, g_bias);
    cudaGetSymbolAddress((void**)&fp,   g_fp);
    cudaGetSymbolAddress((void**)&kb,   g_k);
    cudaGetSymbolAddress((void**)&vb,   g_v);
    cudaGetSymbolAddress((void**)&qb,   g_q);
    cudaGetSymbolAddress((void**)&sh,   g_sh);
    cudaGetSymbolAddress((void**)&samp, g_samp);
    cudaGetSymbolAddress((void**)&attn, g_attn);

    const int NBIG = T_ * HW_ * D_;

    bias_kernel<<<T_ * M_, 256>>>(tracks, fpos, bias);
    add_kernel<<<(NBIG + 255) / 256, 256>>>(features, fpe, fp, NBIG);

    dim3 gBig(D_ / 128, (T_ * HW_) / 128);   // (6, 128)
    dim3 gSm (D_ / 128, (T_ * M_) / 128);    // (6, 32)

    // ---- sampling ----
    gemm_tf32<<<gBig, 256>>>(fp, Wk_s, nullptr, kb, D_);        // K
    layernorm<<<T_ * HW_, 256>>>(kb, kg_s);
    gemm_tf32<<<gBig, 256>>>(features, Wv_s, nullptr, vb, D_);  // V
    gemm_tf32<<<gSm, 256>>>(tpe, Wq_s, nullptr, qb, D_);        // Q
    layernorm<<<T_ * M_, 256>>>(qb, qg_s);

    dim3 gs1(HW_ / 64, M_ / 64, T_ * H_);
    scores_tf32<<<gs1, 256>>>(qb, kb, bias, attn, M_, HW_, 0);
    softmax_rows<<<T_ * H_ * M_, 256>>>(attn, HW_);
    dim3 ga1(1, M_ / 64, T_ * H_);
    av_tf32<<<ga1, 128>>>(attn, vb, sh, M_, HW_);

    gemm_tf32<<<gSm, 256>>>(sh, Wo_s, nullptr, samp, D_);       // sampled

    // ---- splatting ----
    gemm_tf32<<<gBig, 256>>>(fpe, Wq_p, nullptr, fp, D_);       // Q2
    layernorm<<<T_ * HW_, 256>>>(fp, qg_p);
    gemm_tf32<<<gSm, 256>>>(tpe, Wk_p, nullptr, qb, D_);        // K2
    layernorm<<<T_ * M_, 256>>>(qb, kg_p);
    gemm_tf32<<<gSm, 256>>>(samp, Wv_p, nullptr, sh, D_);       // V2

    dim3 gs2(M_ / 64, HW_ / 64, T_ * H_);
    scores_tf32<<<gs2, 256>>>(fp, qb, bias, attn, HW_, M_, 1);
    softmax_rows<<<T_ * H_ * HW_, 256>>>(attn, M_);
    dim3 ga2(1, HW_ / 64, T_ * H_);
    av_tf32<<<ga2, 128>>>(attn, sh, kb, HW_, M_);

    // out = features + updH @ Wout_p^T
    gemm_tf32<<<gBig, 256>>>(kb, Wout_p, features, out, D_);
}

// round 3
// speedup vs baseline: 6.8582x; 2.3263x over previous
#include <cuda_runtime.h>
#include <cuda_bf16.h>
#include <math.h>

#define T_ 16
#define HW_ 1024
#define M_ 256
#define D_ 768
#define H_ 8
#define HD_ 96
#define SCALE_F 0.1020620726159658f  /* 1/sqrt(96) */

typedef __nv_bfloat16 bf16;
typedef __nv_bfloat162 bf162;

// ---------------- scratch (static device globals; no allocation) ----------------
__device__ __align__(256) float g_bias [(size_t)T_ * M_ * HW_];   // [T][M][HW]
__device__ __align__(256) float g_biasT[(size_t)T_ * HW_ * M_];   // [T][HW][M]
__device__ __align__(256) float g_big0 [(size_t)T_ * HW_ * D_];   // fp32 GEMM out (pre-LN)
__device__ __align__(256) float g_sm0  [(size_t)T_ * M_  * D_];   // fp32 small GEMM out
__device__ __align__(256) float g_attn [(size_t)T_ * H_ * M_ * HW_]; // fp32 scores
__device__ __align__(256) bf16 h_feat[(size_t)T_ * HW_ * D_];
__device__ __align__(256) bf16 h_fp  [(size_t)T_ * HW_ * D_];   // featplus / Q2_ln
__device__ __align__(256) bf16 h_fpe [(size_t)T_ * HW_ * D_];
__device__ __align__(256) bf16 h_kb  [(size_t)T_ * HW_ * D_];   // K_ln / upd
__device__ __align__(256) bf16 h_vb  [(size_t)T_ * HW_ * D_];   // V
__device__ __align__(256) bf16 h_tpe [(size_t)T_ * M_ * D_];
__device__ __align__(256) bf16 h_qb  [(size_t)T_ * M_ * D_];    // Q_ln / K2_ln
__device__ __align__(256) bf16 h_sh  [(size_t)T_ * M_ * D_];    // sampled-heads / V2
__device__ __align__(256) bf16 h_samp[(size_t)T_ * M_ * D_];
__device__ __align__(256) bf16 h_attn[(size_t)T_ * H_ * M_ * HW_]; // bf16 probs
__device__ __align__(256) bf16 h_W[8][D_ * D_];

// ---------------- ptx helpers ----------------
__device__ __forceinline__ unsigned cvta_s(const void* p) {
    return (unsigned)__cvta_generic_to_shared(p);
}
#define CP16(dst, src) asm volatile("cp.async.cg.shared.global [%0], [%1], 16;" :: "r"(dst), "l"(src))
#define CPC() asm volatile("cp.async.commit_group;")
#define CPW(n) asm volatile("cp.async.wait_group %0;" :: "n"(n))

__device__ __forceinline__ void ldsm4(unsigned a, unsigned& r0, unsigned& r1, unsigned& r2, unsigned& r3) {
    asm volatile("ldmatrix.sync.aligned.m8n8.x4.shared.b16 {%0,%1,%2,%3}, [%4];"
                 : "=r"(r0), "=r"(r1), "=r"(r2), "=r"(r3) : "r"(a));
}
__device__ __forceinline__ void ldsm4t(unsigned a, unsigned& r0, unsigned& r1, unsigned& r2, unsigned& r3) {
    asm volatile("ldmatrix.sync.aligned.m8n8.x4.trans.shared.b16 {%0,%1,%2,%3}, [%4];"
                 : "=r"(r0), "=r"(r1), "=r"(r2), "=r"(r3) : "r"(a));
}
__device__ __forceinline__ void mma_bf16(float* c,
    unsigned a0, unsigned a1, unsigned a2, unsigned a3, unsigned b0, unsigned b1) {
    asm volatile(
        "mma.sync.aligned.m16n8k16.row.col.f32.bf16.bf16.f32 "
        "{%0,%1,%2,%3},{%4,%5,%6,%7},{%8,%9},{%0,%1,%2,%3};"
        : "+f"(c[0]), "+f"(c[1]), "+f"(c[2]), "+f"(c[3])
        : "r"(a0), "r"(a1), "r"(a2), "r"(a3), "r"(b0), "r"(b1));
}

// swizzled bf16-unit offset in a [rows][32] bf16 tile (2 rows share a 128B line;
// 16B chunks xor-permuted by line index -> conflict-free ldmatrix + cp.async)
__device__ __forceinline__ unsigned swz(int row, int g) {
    return ((row >> 1) << 6) | (((((row & 1) << 2) | g) ^ ((row >> 1) & 7)) << 3);
}

// ---------------- small utility kernels ----------------
__global__ __launch_bounds__(256) void cvt4(const float* __restrict__ s, bf16* __restrict__ d, int n4) {
    int i = blockIdx.x * 256 + threadIdx.x;
    if (i < n4) {
        float4 v = ((const float4*)s)[i];
        ((bf162*)d)[2 * i]     = __floats2bfloat162_rn(v.x, v.y);
        ((bf162*)d)[2 * i + 1] = __floats2bfloat162_rn(v.z, v.w);
    }
}
__global__ __launch_bounds__(256) void addcvt4(const float* __restrict__ a, const float* __restrict__ b,
                                               bf16* __restrict__ d, int n4) {
    int i = blockIdx.x * 256 + threadIdx.x;
    if (i < n4) {
        float4 x = ((const float4*)a)[i];
        float4 y = ((const float4*)b)[i];
        ((bf162*)d)[2 * i]     = __floats2bfloat162_rn(x.x + y.x, x.y + y.y);
        ((bf162*)d)[2 * i + 1] = __floats2bfloat162_rn(x.z + y.z, x.w + y.w);
    }
}
__global__ __launch_bounds__(256) void bias_kernel(
    const float* __restrict__ tracks, const float* __restrict__ fpos, float* __restrict__ bias) {
    int tm = blockIdx.x;
    float px = tracks[2 * tm], py = tracks[2 * tm + 1];
    float* brow = bias + (size_t)tm * HW_;
    for (int n = threadIdx.x; n < HW_; n += 256) {
        float dx = px - fpos[2 * n], dy = py - fpos[2 * n + 1];
        brow[n] = -2.0f * (dx * dx + dy * dy);
    }
}
__global__ __launch_bounds__(256) void biasT_kernel(
    const float* __restrict__ tracks, const float* __restrict__ fpos, float* __restrict__ biasT) {
    int tn = blockIdx.x;                    // t*HW + n
    int t = tn >> 10, n = tn & 1023;
    float fx = fpos[2 * n], fy = fpos[2 * n + 1];
    float* brow = biasT + (size_t)tn * M_;
    int m = threadIdx.x;
    if (m < M_) {
        float dx = tracks[(t * M_ + m) * 2] - fx;
        float dy = tracks[(t * M_ + m) * 2 + 1] - fy;
        brow[m] = -2.0f * (dx * dx + dy * dy);
    }
}

// ---------------- LayerNorm: fp32 in -> bf16 out ----------------
__global__ __launch_bounds__(256) void ln_h(const float* __restrict__ X,
                                            const float* __restrict__ g, bf16* __restrict__ Y) {
    const float* row = X + (size_t)blockIdx.x * D_;
    bf16* orow = Y + (size_t)blockIdx.x * D_;
    int tid = threadIdx.x;
    float v0 = row[tid], v1 = row[tid + 256], v2 = row[tid + 512];
    __shared__ float red[256];
    red[tid] = v0 + v1 + v2;
    __syncthreads();
    for (int s = 128; s > 0; s >>= 1) { if (tid < s) red[tid] += red[tid + s]; __syncthreads(); }
    float mean = red[0] * (1.0f / 768.0f);
    __syncthreads();
    float d0 = v0 - mean, d1 = v1 - mean, d2 = v2 - mean;
    red[tid] = d0 * d0 + d1 * d1 + d2 * d2;
    __syncthreads();
    for (int s = 128; s > 0; s >>= 1) { if (tid < s) red[tid] += red[tid + s]; __syncthreads(); }
    float inv = rsqrtf(red[0] * (1.0f / 768.0f) + 1e-6f);
    orow[tid]       = __float2bfloat16(d0 * inv * g[tid]);
    orow[tid + 256] = __float2bfloat16(d1 * inv * g[tid + 256]);
    orow[tid + 512] = __float2bfloat16(d2 * inv * g[tid + 512]);
}

// ---------------- dense GEMM: C[R,768] = A[R,768] @ W[768,768]^T ----------------
// bf16 in (gmem), cp.async double-buffered, ldmatrix + mma.m16n8k16, fp32/bf16 out.
__global__ __launch_bounds__(256) void gemm_h(
    const bf16* __restrict__ A, const bf16* __restrict__ W,
    const float* __restrict__ addsrc, float* __restrict__ Cf, bf16* __restrict__ Ch)
{
    __shared__ bf16 sA[2][128 * 32], sW[2][128 * 32];
    const int tid = threadIdx.x, lane = tid & 31, warp = tid >> 5;
    const int wm = warp & 3, wn = warp >> 2;
    const int bm = blockIdx.y * 128, bn = blockIdx.x * 128;
    unsigned aU = cvta_s(sA), wU = cvta_s(sW);
    const int r0 = tid >> 2, r1 = r0 + 64, gg = tid & 3;
    const bf16* As0 = A + (size_t)(bm + r0) * D_ + gg * 8;
    const bf16* As1 = A + (size_t)(bm + r1) * D_ + gg * 8;
    const bf16* Ws0 = W + (size_t)(bn + r0) * D_ + gg * 8;
    const bf16* Ws1 = W + (size_t)(bn + r1) * D_ + gg * 8;
    const unsigned dA0 = aU + (swz(r0, gg) << 1), dA1 = aU + (swz(r1, gg) << 1);
    const unsigned dW0 = wU + (swz(r0, gg) << 1), dW1 = wU + (swz(r1, gg) << 1);

    float c[2][8][4] = {};

    CP16(dA0, As0); CP16(dA1, As1); CP16(dW0, Ws0); CP16(dW1, Ws1); CPC();

    const int ITERS = D_ / 32;  // 24
    for (int it = 0; it < ITERS; ++it) {
        int buf = it & 1;
        if (it + 1 < ITERS) {
            int k0 = (it + 1) * 32;
            unsigned o = (buf ^ 1) * 8192;
            CP16(dA0 + o, As0 + k0); CP16(dA1 + o, As1 + k0);
            CP16(dW0 + o, Ws0 + k0); CP16(dW1 + o, Ws1 + k0);
            CPC(); CPW(1);
        } else CPW(0);
        __syncthreads();
        unsigned ab = aU + buf * 8192, wb = wU + buf * 8192;
        const int rlow = lane & 15, khalf = lane >> 4;
#pragma unroll
        for (int kk = 0; kk < 32; kk += 16) {
            int g = (kk >> 3) + khalf;
            unsigned a[2][4], bfr[4][4];
#pragma unroll
            for (int mt = 0; mt < 2; mt++) {
                int row = wm * 32 + mt * 16 + rlow;
                ldsm4(ab + (swz(row, g) << 1), a[mt][0], a[mt][1], a[mt][2], a[mt][3]);
            }
#pragma unroll
            for (int bt = 0; bt < 4; bt++) {
                int row = wn * 64 + bt * 16 + rlow;
                ldsm4(wb + (swz(row, g) << 1), bfr[bt][0], bfr[bt][1], bfr[bt][2], bfr[bt][3]);
            }
#pragma unroll
            for (int mt = 0; mt < 2; mt++)
#pragma unroll
                for (int nt = 0; nt < 8; nt++) {
                    int bt = nt >> 1, hi = nt & 1;
                    mma_bf16(c[mt][nt], a[mt][0], a[mt][1], a[mt][2], a[mt][3],
                             bfr[bt][hi ? 1 : 0], bfr[bt][hi ? 3 : 2]);
                }
        }
        __syncthreads();
    }

    const int ml = lane >> 2, nl = 2 * (lane & 3);
#pragma unroll
    for (int mt = 0; mt < 2; mt++) {
        int m0 = bm + wm * 32 + mt * 16 + ml;
#pragma unroll
        for (int nt = 0; nt < 8; nt++) {
            int n0 = bn + wn * 64 + nt * 8 + nl;
            size_t o0 = (size_t)m0 * D_ + n0, o1 = o0 + (size_t)8 * D_;
            float x0 = c[mt][nt][0], x1 = c[mt][nt][1];
            float y0 = c[mt][nt][2], y1 = c[mt][nt][3];
            if (addsrc) {
                float2 s0 = *(const float2*)(addsrc + o0);
                float2 s1 = *(const float2*)(addsrc + o1);
                x0 += s0.x; x1 += s0.y; y0 += s1.x; y1 += s1.y;
            }
            if (Cf) {
                *(float2*)(Cf + o0) = make_float2(x0, x1);
                *(float2*)(Cf + o1) = make_float2(y0, y1);
            }
            if (Ch) {
                *(bf162*)(Ch + o0) = __floats2bfloat162_rn(x0, x1);
                *(bf162*)(Ch + o1) = __floats2bfloat162_rn(y0, y1);
            }
        }
    }
}

// ---------------- attention scores: S[z][q][k] = Q.K^T * scale + bias ----------------
// bf16 Q/K head slices (row stride 768), K-depth 96 (3 iters), fp32 out.
__global__ __launch_bounds__(256) void scores_h(
    const bf16* __restrict__ Q, const bf16* __restrict__ Kk,
    const float* __restrict__ Bias, float* __restrict__ S, int Mq, int Nk)
{
    __shared__ bf16 sA[2][128 * 32], sB[2][128 * 32];
    const int z = blockIdx.z, t = z >> 3, h = z & 7;
    const bf16* Qb = Q + (size_t)t * Mq * D_ + h * HD_;
    const bf16* Kb = Kk + (size_t)t * Nk * D_ + h * HD_;
    const float* Bb = Bias + (size_t)t * M_ * HW_;
    float* Sb = S + (size_t)z * Mq * Nk;

    const int tid = threadIdx.x, lane = tid & 31, warp = tid >> 5;
    const int wm = warp & 3, wn = warp >> 2;
    const int bm = blockIdx.y * 128, bn = blockIdx.x * 128;
    unsigned aU = cvta_s(sA), bU = cvta_s(sB);
    const int r0 = tid >> 2, r1 = r0 + 64, gg = tid & 3;
    const bf16* Qs0 = Qb + (size_t)(bm + r0) * D_ + gg * 8;
    const bf16* Qs1 = Qb + (size_t)(bm + r1) * D_ + gg * 8;
    const bf16* Ks0 = Kb + (size_t)(bn + r0) * D_ + gg * 8;
    const bf16* Ks1 = Kb + (size_t)(bn + r1) * D_ + gg * 8;
    const unsigned dA0 = aU + (swz(r0, gg) << 1), dA1 = aU + (swz(r1, gg) << 1);
    const unsigned dB0 = bU + (swz(r0, gg) << 1), dB1 = bU + (swz(r1, gg) << 1);

    float c[2][8][4] = {};

    CP16(dA0, Qs0); CP16(dA1, Qs1); CP16(dB0, Ks0); CP16(dB1, Ks1); CPC();

    const int ITERS = 3;  // 96/32
    for (int it = 0; it < ITERS; ++it) {
        int buf = it & 1;
        if (it + 1 < ITERS) {
            int k0 = (it + 1) * 32;
            unsigned o = (buf ^ 1) * 8192;
            CP16(dA0 + o, Qs0 + k0); CP16(dA1 + o, Qs1 + k0);
            CP16(dB0 + o, Ks0 + k0); CP16(dB1 + o, Ks1 + k0);
            CPC(); CPW(1);
        } else CPW(0);
        __syncthreads();
        unsigned ab = aU + buf * 8192, bb = bU + buf * 8192;
        const int rlow = lane & 15, khalf = lane >> 4;
#pragma unroll
        for (int kk = 0; kk < 32; kk += 16) {
            int g = (kk >> 3) + khalf;
            unsigned a[2][4], bfr[4][4];
#pragma unroll
            for (int mt = 0; mt < 2; mt++) {
                int row = wm * 32 + mt * 16 + rlow;
                ldsm4(ab + (swz(row, g) << 1), a[mt][0], a[mt][1], a[mt][2], a[mt][3]);
            }
#pragma unroll
            for (int bt = 0; bt < 4; bt++) {
                int row = wn * 64 + bt * 16 + rlow;
                ldsm4(bb + (swz(row, g) << 1), bfr[bt][0], bfr[bt][1], bfr[bt][2], bfr[bt][3]);
            }
#pragma unroll
            for (int mt = 0; mt < 2; mt++)
#pragma unroll
                for (int nt = 0; nt < 8; nt++) {
                    int bt = nt >> 1, hi = nt & 1;
                    mma_bf16(c[mt][nt], a[mt][0], a[mt][1], a[mt][2], a[mt][3],
                             bfr[bt][hi ? 1 : 0], bfr[bt][hi ? 3 : 2]);
                }
        }
        __syncthreads();
    }

    const int ml = lane >> 2, nl = 2 * (lane & 3);
#pragma unroll
    for (int mt = 0; mt < 2; mt++) {
        int m0 = bm + wm * 32 + mt * 16 + ml;
#pragma unroll
        for (int nt = 0; nt < 8; nt++) {
            int n0 = bn + wn * 64 + nt * 8 + nl;
            float2 b0 = *(const float2*)(Bb + (size_t)m0 * Nk + n0);
            float2 b1 = *(const float2*)(Bb + (size_t)(m0 + 8) * Nk + n0);
            *(float2*)(Sb + (size_t)m0 * Nk + n0) =
                make_float2(c[mt][nt][0] * SCALE_F + b0.x, c[mt][nt][1] * SCALE_F + b0.y);
            *(float2*)(Sb + (size_t)(m0 + 8) * Nk + n0) =
                make_float2(c[mt][nt][2] * SCALE_F + b1.x, c[mt][nt][3] * SCALE_F + b1.y);
        }
    }
}

// ---------------- warp-per-row softmax: fp32 in, bf16 out ----------------
template <int L>
__global__ __launch_bounds__(256) void softmax_w(const float* __restrict__ S, bf16* __restrict__ P) {
    int w = threadIdx.x >> 5, lane = threadIdx.x & 31;
    size_t row = (size_t)blockIdx.x * 8 + w;
    const float2* src = (const float2*)(S + row * L);
    bf162* dst = (bf162*)(P + row * L);
    const int NP = L / 64;
    float2 v[NP];
    float mx = -1e30f;
#pragma unroll
    for (int i = 0; i < NP; i++) {
        v[i] = src[lane + i * 32];
        mx = fmaxf(mx, fmaxf(v[i].x, v[i].y));
    }
#pragma unroll
    for (int o = 16; o; o >>= 1) mx = fmaxf(mx, __shfl_xor_sync(~0u, mx, o));
    float sum = 0.0f;
#pragma unroll
    for (int i = 0; i < NP; i++) {
        v[i].x = __expf(v[i].x - mx);
        v[i].y = __expf(v[i].y - mx);
        sum += v[i].x + v[i].y;
    }
#pragma unroll
    for (int o = 16; o; o >>= 1) sum += __shfl_xor_sync(~0u, sum, o);
    float inv = 1.0f / sum;
#pragma unroll
    for (int i = 0; i < NP; i++)
        dst[lane + i * 32] = __floats2bfloat162_rn(v[i].x * inv, v[i].y * inv);
}

// ---------------- AV: O[t,m,h*96+:96] = P[z] @ V_h, bf16 out ----------------
// P: [z][Mq][Kn] bf16; V: [t][k][768] head slice via ldmatrix.trans.
__global__ __launch_bounds__(256) void av_h(
    const bf16* __restrict__ P, const bf16* __restrict__ V,
    bf16* __restrict__ O, int Mq, int Kn)
{
    __shared__ bf16 sP[2][128 * 32];
    __shared__ bf16 sV[2][32 * 104];
    const int z = blockIdx.y, t = z >> 3, h = z & 7;
    const bf16* Pb = P + (size_t)z * Mq * Kn;
    const bf16* Vb = V + (size_t)t * Kn * D_ + h * HD_;
    bf16* Ob = O + (size_t)t * Mq * D_ + h * HD_;
    const int tid = threadIdx.x, lane = tid & 31, w = tid >> 5;
    const int bm = blockIdx.x * 128;
    unsigned pU = cvta_s(sP), vU = cvta_s(sV);

    const int r0 = tid >> 2, r1 = r0 + 64, gg = tid & 3;
    const bf16* Ps0 = Pb + (size_t)(bm + r0) * Kn + gg * 8;
    const bf16* Ps1 = Pb + (size_t)(bm + r1) * Kn + gg * 8;
    const unsigned dP0 = pU + (swz(r0, gg) << 1), dP1 = pU + (swz(r1, gg) << 1);
    const int vr0 = tid / 12, vg0 = tid % 12;
    const int vc1 = tid + 256, vr1 = vc1 / 12, vg1 = vc1 % 12;
    const bool v1ok = vc1 < 384;
    const bf16* Vs0 = Vb + (size_t)vr0 * D_ + vg0 * 8;
    const bf16* Vs1 = Vb + (size_t)vr1 * D_ + vg1 * 8;
    const unsigned dV0 = vU + vr0 * 208 + vg0 * 16;
    const unsigned dV1 = vU + vr1 * 208 + vg1 * 16;

    float c[12][4] = {};

    CP16(dP0, Ps0); CP16(dP1, Ps1);
    CP16(dV0, Vs0);
    if (v1ok) CP16(dV1, Vs1);
    CPC();

    const int ITERS = Kn / 32;
    for (int it = 0; it < ITERS; ++it) {
        int buf = it & 1;
        if (it + 1 < ITERS) {
            int k0 = (it + 1) * 32;
            unsigned op = (buf ^ 1) * 8192, ov = (buf ^ 1) * 6656;
            CP16(dP0 + op, Ps0 + k0); CP16(dP1 + op, Ps1 + k0);
            CP16(dV0 + ov, Vs0 + (size_t)k0 * D_);
            if (v1ok) CP16(dV1 + ov, Vs1 + (size_t)k0 * D_);
            CPC(); CPW(1);
        } else CPW(0);
        __syncthreads();
        unsigned pb = pU + buf * 8192, vb = vU + buf * 6656;
        const int rlow = lane & 15, khalf = lane >> 4;
#pragma unroll
        for (int kk = 0; kk < 32; kk += 16) {
            int g = (kk >> 3) + khalf;
            unsigned a0, a1, a2, a3;
            int row = w * 16 + rlow;
            ldsm4(pb + (swz(row, g) << 1), a0, a1, a2, a3);
#pragma unroll
            for (int p = 0; p < 6; p++) {
                unsigned baddr = vb + (kk + rlow) * 208 + (p * 16 + khalf * 8) * 2;
                unsigned b0, b1, b2, b3;
                ldsm4t(baddr, b0, b1, b2, b3);
                mma_bf16(c[2 * p],     a0, a1, a2, a3, b0, b1);
                mma_bf16(c[2 * p + 1], a0, a1, a2, a3, b2, b3);
            }
        }
        __syncthreads();
    }

    const int ml = lane >> 2, nl = 2 * (lane & 3);
#pragma unroll
    for (int nt = 0; nt < 12; nt++) {
        int n0 = nt * 8 + nl;
        int m0 = bm + w * 16 + ml;
        *(bf162*)(Ob + (size_t)m0 * D_ + n0)       = __floats2bfloat162_rn(c[nt][0], c[nt][1]);
        *(bf162*)(Ob + (size_t)(m0 + 8) * D_ + n0) = __floats2bfloat162_rn(c[nt][2], c[nt][3]);
    }
}

// =================================================================================
extern "C" void kernel_launch(void* const* d_in, const int* in_sizes, int n_in,
                              void* d_out, int out_size)
{
    const float* features = (const float*)d_in[0];
    const float* tracks   = (const float*)d_in[1];
    const float* fpos     = (const float*)d_in[2];
    const float* tpe      = (const float*)d_in[3];
    const float* fpe      = (const float*)d_in[4];
    const float* Wf[8] = {
        (const float*)d_in[5],   // Wq_s
        (const float*)d_in[6],   // Wk_s
        (const float*)d_in[7],   // Wv_s
        (const float*)d_in[10],  // Wo_s
        (const float*)d_in[11],  // Wq_p
        (const float*)d_in[12],  // Wk_p
        (const float*)d_in[13],  // Wv_p
        (const float*)d_in[16],  // Wout_p
    };
    const float* qg_s = (const float*)d_in[8];
    const float* kg_s = (const float*)d_in[9];
    const float* qg_p = (const float*)d_in[14];
    const float* kg_p = (const float*)d_in[15];
    float* out = (float*)d_out;

    float *bias, *biasT, *big0, *sm0, *attn;
    bf16 *feat_h, *fp_h, *fpe_h, *kb_h, *vb_h, *tpe_h, *qb_h, *sh_h, *samp_h, *attn_h, *w_h;
    cudaGetSymbolAddress((void**)&bias,  g_bias);
    cudaGetSymbolAddress((void**)&biasT, g_biasT);
    cudaGetSymbolAddress((void**)&big0,  g_big0);
    cudaGetSymbolAddress((void**)&sm0,   g_sm0);
    cudaGetSymbolAddress((void**)&attn,  g_attn);
    cudaGetSymbolAddress((void**)&feat_h, h_feat);
    cudaGetSymbolAddress((void**)&fp_h,   h_fp);
    cudaGetSymbolAddress((void**)&fpe_h,  h_fpe);
    cudaGetSymbolAddress((void**)&kb_h,   h_kb);
    cudaGetSymbolAddress((void**)&vb_h,   h_vb);
    cudaGetSymbolAddress((void**)&tpe_h,  h_tpe);
    cudaGetSymbolAddress((void**)&qb_h,   h_qb);
    cudaGetSymbolAddress((void**)&sh_h,   h_sh);
    cudaGetSymbolAddress((void**)&samp_h, h_samp);
    cudaGetSymbolAddress((void**)&attn_h, h_attn);
    cudaGetSymbolAddress((void**)&w_h,    h_W);

    const int NBIG = T_ * HW_ * D_;         // 12,582,912
    const int NSM  = T_ * M_ * D_;          // 3,145,728
    const int NW   = D_ * D_;               // 589,824

    // conversions
    cvt4<<<NBIG / 1024, 256>>>(features, feat_h, NBIG / 4);
    cvt4<<<NBIG / 1024, 256>>>(fpe, fpe_h, NBIG / 4);
    cvt4<<<NSM / 1024, 256>>>(tpe, tpe_h, NSM / 4);
    addcvt4<<<NBIG / 1024, 256>>>(features, fpe, fp_h, NBIG / 4);
    for (int i = 0; i < 8; i++)
        cvt4<<<NW / 1024, 256>>>(Wf[i], w_h + (size_t)i * NW, NW / 4);

    bias_kernel<<<T_ * M_, 256>>>(tracks, fpos, bias);
    biasT_kernel<<<T_ * HW_, 256>>>(tracks, fpos, biasT);

    dim3 gBig(6, 128);   // 768/128 x 16384/128
    dim3 gSm(6, 32);

    // ---- sampling ----
    gemm_h<<<gBig, 256>>>(fp_h, w_h + 1 * (size_t)NW, nullptr, big0, nullptr);   // K
    ln_h<<<T_ * HW_, 256>>>(big0, kg_s, kb_h);
    gemm_h<<<gBig, 256>>>(feat_h, w_h + 2 * (size_t)NW, nullptr, nullptr, vb_h); // V (bf16 only)
    gemm_h<<<gSm, 256>>>(tpe_h, w_h + 0 * (size_t)NW, nullptr, sm0, nullptr);    // Q
    ln_h<<<T_ * M_, 256>>>(sm0, qg_s, qb_h);

    scores_h<<<dim3(HW_ / 128, M_ / 128, T_ * H_), 256>>>(qb_h, kb_h, bias, attn, M_, HW_);
    softmax_w<HW_><<<(T_ * H_ * M_) / 8, 256>>>(attn, attn_h);
    av_h<<<dim3(M_ / 128, T_ * H_), 256>>>(attn_h, vb_h, sh_h, M_, HW_);

    gemm_h<<<gSm, 256>>>(sh_h, w_h + 3 * (size_t)NW, nullptr, nullptr, samp_h);  // sampled

    // ---- splatting ----
    gemm_h<<<gBig, 256>>>(fpe_h, w_h + 4 * (size_t)NW, nullptr, big0, nullptr);  // Q2
    ln_h<<<T_ * HW_, 256>>>(big0, qg_p, fp_h);
    gemm_h<<<gSm, 256>>>(tpe_h, w_h + 5 * (size_t)NW, nullptr, sm0, nullptr);    // K2
    ln_h<<<T_ * M_, 256>>>(sm0, kg_p, qb_h);
    gemm_h<<<gSm, 256>>>(samp_h, w_h + 6 * (size_t)NW, nullptr, nullptr, sh_h);  // V2

    scores_h<<<dim3(M_ / 128, HW_ / 128, T_ * H_), 256>>>(fp_h, qb_h, biasT, attn, HW_, M_);
    softmax_w<M_><<<(T_ * H_ * HW_) / 8, 256>>>(attn, attn_h);
    av_h<<<dim3(HW_ / 128, T_ * H_), 256>>>(attn_h, sh_h, kb_h, HW_, M_);

    // out = features + upd @ Wout^T
    gemm_h<<<gBig, 256>>>(kb_h, w_h + 7 * (size_t)NW, features, out, nullptr);
}

// round 4
// speedup vs baseline: 8.4769x; 1.2360x over previous
#include <cuda_runtime.h>
#include <cuda_bf16.h>
#include <math.h>

#define T_ 16
#define HW_ 1024
#define M_ 256
#define D_ 768
#define H_ 8
#define HD_ 96
#define SCALE_F 0.1020620726159658f  /* 1/sqrt(96) */

typedef __nv_bfloat16 bf16;
typedef __nv_bfloat162 bf162;

// ---------------- scratch (static device globals; no allocation) ----------------
__device__ __align__(256) bf16 h_feat[(size_t)T_ * HW_ * D_];
__device__ __align__(256) bf16 h_fp  [(size_t)T_ * HW_ * D_];   // featplus / Q2_ln
__device__ __align__(256) bf16 h_fpe [(size_t)T_ * HW_ * D_];
__device__ __align__(256) bf16 h_kb  [(size_t)T_ * HW_ * D_];   // K_ln / upd
__device__ __align__(256) bf16 h_vb  [(size_t)T_ * HW_ * D_];   // V
__device__ __align__(256) bf16 h_big0[(size_t)T_ * HW_ * D_];   // pre-LN scratch (big)
__device__ __align__(256) bf16 h_tpe [(size_t)T_ * M_ * D_];
__device__ __align__(256) bf16 h_qb  [(size_t)T_ * M_ * D_];    // Q_ln / K2_ln
__device__ __align__(256) bf16 h_sh  [(size_t)T_ * M_ * D_];    // sampled-heads / V2
__device__ __align__(256) bf16 h_samp[(size_t)T_ * M_ * D_];
__device__ __align__(256) bf16 h_sm0 [(size_t)T_ * M_ * D_];    // pre-LN scratch (small)
__device__ __align__(256) bf16 h_W[8][D_ * D_];

// ---------------- ptx helpers ----------------
__device__ __forceinline__ unsigned cvta_s(const void* p) {
    return (unsigned)__cvta_generic_to_shared(p);
}
#define CP16(dst, src) asm volatile("cp.async.cg.shared.global [%0], [%1], 16;" :: "r"(dst), "l"(src))
#define CPC() asm volatile("cp.async.commit_group;")
#define CPW(n) asm volatile("cp.async.wait_group %0;" :: "n"(n))

__device__ __forceinline__ void ldsm4(unsigned a, unsigned& r0, unsigned& r1, unsigned& r2, unsigned& r3) {
    asm volatile("ldmatrix.sync.aligned.m8n8.x4.shared.b16 {%0,%1,%2,%3}, [%4];"
                 : "=r"(r0), "=r"(r1), "=r"(r2), "=r"(r3) : "r"(a));
}
__device__ __forceinline__ void ldsm4t(unsigned a, unsigned& r0, unsigned& r1, unsigned& r2, unsigned& r3) {
    asm volatile("ldmatrix.sync.aligned.m8n8.x4.trans.shared.b16 {%0,%1,%2,%3}, [%4];"
                 : "=r"(r0), "=r"(r1), "=r"(r2), "=r"(r3) : "r"(a));
}
__device__ __forceinline__ void mma_bf16(float* c,
    unsigned a0, unsigned a1, unsigned a2, unsigned a3, unsigned b0, unsigned b1) {
    asm volatile(
        "mma.sync.aligned.m16n8k16.row.col.f32.bf16.bf16.f32 "
        "{%0,%1,%2,%3},{%4,%5,%6,%7},{%8,%9},{%0,%1,%2,%3};"
        : "+f"(c[0]), "+f"(c[1]), "+f"(c[2]), "+f"(c[3])
        : "r"(a0), "r"(a1), "r"(a2), "r"(a3), "r"(b0), "r"(b1));
}
__device__ __forceinline__ unsigned packbf(float x, float y) {
    bf162 v = __floats2bfloat162_rn(x, y);
    return *reinterpret_cast<unsigned*>(&v);
}
// swizzled bf16-unit offset in a [rows][32] bf16 tile
__device__ __forceinline__ unsigned swz(int row, int g) {
    return ((row >> 1) << 6) | (((((row & 1) << 2) | g) ^ ((row >> 1) & 7)) << 3);
}

// ---------------- conversions ----------------
__global__ __launch_bounds__(256) void cvt3(const float* __restrict__ f, const float* __restrict__ pe,
                                            bf16* __restrict__ feat, bf16* __restrict__ fpeh,
                                            bf16* __restrict__ fph, int n4) {
    int i = blockIdx.x * 256 + threadIdx.x;
    if (i < n4) {
        float4 x = ((const float4*)f)[i];
        float4 y = ((const float4*)pe)[i];
        ((bf162*)feat)[2 * i]     = __floats2bfloat162_rn(x.x, x.y);
        ((bf162*)feat)[2 * i + 1] = __floats2bfloat162_rn(x.z, x.w);
        ((bf162*)fpeh)[2 * i]     = __floats2bfloat162_rn(y.x, y.y);
        ((bf162*)fpeh)[2 * i + 1] = __floats2bfloat162_rn(y.z, y.w);
        ((bf162*)fph)[2 * i]      = __floats2bfloat162_rn(x.x + y.x, x.y + y.y);
        ((bf162*)fph)[2 * i + 1]  = __floats2bfloat162_rn(x.z + y.z, x.w + y.w);
    }
}
__global__ __launch_bounds__(256) void cvt4(const float* __restrict__ s, bf16* __restrict__ d, int n4) {
    int i = blockIdx.x * 256 + threadIdx.x;
    if (i < n4) {
        float4 v = ((const float4*)s)[i];
        ((bf162*)d)[2 * i]     = __floats2bfloat162_rn(v.x, v.y);
        ((bf162*)d)[2 * i + 1] = __floats2bfloat162_rn(v.z, v.w);
    }
}
struct WP { const float* p[8]; };
__global__ __launch_bounds__(256) void cvtw(WP wp, bf16* __restrict__ dst) {
    int wi = blockIdx.y;
    const float* s = wp.p[wi];
    bf16* d = dst + (size_t)wi * (D_ * D_);
    int i = blockIdx.x * 256 + threadIdx.x;   // n4 = D_*D_/4
    float4 v = ((const float4*)s)[i];
    ((bf162*)d)[2 * i]     = __floats2bfloat162_rn(v.x, v.y);
    ((bf162*)d)[2 * i + 1] = __floats2bfloat162_rn(v.z, v.w);
}

// ---------------- LayerNorm: bf16 in -> bf16 out ----------------
__global__ __launch_bounds__(256) void ln_bh(const bf16* __restrict__ X,
                                             const float* __restrict__ g, bf16* __restrict__ Y) {
    const bf16* row = X + (size_t)blockIdx.x * D_;
    bf16* orow = Y + (size_t)blockIdx.x * D_;
    int tid = threadIdx.x;
    float v0 = __bfloat162float(row[tid]);
    float v1 = __bfloat162float(row[tid + 256]);
    float v2 = __bfloat162float(row[tid + 512]);
    __shared__ float red[256];
    red[tid] = v0 + v1 + v2;
    __syncthreads();
    for (int s = 128; s > 0; s >>= 1) { if (tid < s) red[tid] += red[tid + s]; __syncthreads(); }
    float mean = red[0] * (1.0f / 768.0f);
    __syncthreads();
    float d0 = v0 - mean, d1 = v1 - mean, d2 = v2 - mean;
    red[tid] = d0 * d0 + d1 * d1 + d2 * d2;
    __syncthreads();
    for (int s = 128; s > 0; s >>= 1) { if (tid < s) red[tid] += red[tid + s]; __syncthreads(); }
    float inv = rsqrtf(red[0] * (1.0f / 768.0f) + 1e-6f);
    orow[tid]       = __float2bfloat16(d0 * inv * g[tid]);
    orow[tid + 256] = __float2bfloat16(d1 * inv * g[tid + 256]);
    orow[tid + 512] = __float2bfloat16(d2 * inv * g[tid + 512]);
}

// ---------------- dense GEMM: C[R,768] = A[R,768] @ W[768,768]^T ----------------
__global__ __launch_bounds__(256) void gemm_h(
    const bf16* __restrict__ A, const bf16* __restrict__ W,
    const float* __restrict__ addsrc, float* __restrict__ Cf, bf16* __restrict__ Ch)
{
    __shared__ bf16 sA[2][128 * 32], sW[2][128 * 32];
    const int tid = threadIdx.x, lane = tid & 31, warp = tid >> 5;
    const int wm = warp & 3, wn = warp >> 2;
    const int bm = blockIdx.y * 128, bn = blockIdx.x * 128;
    unsigned aU = cvta_s(sA), wU = cvta_s(sW);
    const int r0 = tid >> 2, r1 = r0 + 64, gg = tid & 3;
    const bf16* As0 = A + (size_t)(bm + r0) * D_ + gg * 8;
    const bf16* As1 = A + (size_t)(bm + r1) * D_ + gg * 8;
    const bf16* Ws0 = W + (size_t)(bn + r0) * D_ + gg * 8;
    const bf16* Ws1 = W + (size_t)(bn + r1) * D_ + gg * 8;
    const unsigned dA0 = aU + (swz(r0, gg) << 1), dA1 = aU + (swz(r1, gg) << 1);
    const unsigned dW0 = wU + (swz(r0, gg) << 1), dW1 = wU + (swz(r1, gg) << 1);

    float c[2][8][4] = {};

    CP16(dA0, As0); CP16(dA1, As1); CP16(dW0, Ws0); CP16(dW1, Ws1); CPC();

    const int ITERS = D_ / 32;  // 24
    for (int it = 0; it < ITERS; ++it) {
        int buf = it & 1;
        if (it + 1 < ITERS) {
            int k0 = (it + 1) * 32;
            unsigned o = (buf ^ 1) * 8192;
            CP16(dA0 + o, As0 + k0); CP16(dA1 + o, As1 + k0);
            CP16(dW0 + o, Ws0 + k0); CP16(dW1 + o, Ws1 + k0);
            CPC(); CPW(1);
        } else CPW(0);
        __syncthreads();
        unsigned ab = aU + buf * 8192, wb = wU + buf * 8192;
        const int rlow = lane & 15, khalf = lane >> 4;
#pragma unroll
        for (int kk = 0; kk < 32; kk += 16) {
            int g = (kk >> 3) + khalf;
            unsigned a[2][4], bfr[4][4];
#pragma unroll
            for (int mt = 0; mt < 2; mt++) {
                int row = wm * 32 + mt * 16 + rlow;
                ldsm4(ab + (swz(row, g) << 1), a[mt][0], a[mt][1], a[mt][2], a[mt][3]);
            }
#pragma unroll
            for (int bt = 0; bt < 4; bt++) {
                int row = wn * 64 + bt * 16 + rlow;
                ldsm4(wb + (swz(row, g) << 1), bfr[bt][0], bfr[bt][1], bfr[bt][2], bfr[bt][3]);
            }
#pragma unroll
            for (int mt = 0; mt < 2; mt++)
#pragma unroll
                for (int nt = 0; nt < 8; nt++) {
                    int bt = nt >> 1, hi = nt & 1;
                    mma_bf16(c[mt][nt], a[mt][0], a[mt][1], a[mt][2], a[mt][3],
                             bfr[bt][hi ? 1 : 0], bfr[bt][hi ? 3 : 2]);
                }
        }
        __syncthreads();
    }

    const int ml = lane >> 2, nl = 2 * (lane & 3);
#pragma unroll
    for (int mt = 0; mt < 2; mt++) {
        int m0 = bm + wm * 32 + mt * 16 + ml;
#pragma unroll
        for (int nt = 0; nt < 8; nt++) {
            int n0 = bn + wn * 64 + nt * 8 + nl;
            size_t o0 = (size_t)m0 * D_ + n0, o1 = o0 + (size_t)8 * D_;
            float x0 = c[mt][nt][0], x1 = c[mt][nt][1];
            float y0 = c[mt][nt][2], y1 = c[mt][nt][3];
            if (addsrc) {
                float2 s0 = *(const float2*)(addsrc + o0);
                float2 s1 = *(const float2*)(addsrc + o1);
                x0 += s0.x; x1 += s0.y; y0 += s1.x; y1 += s1.y;
            }
            if (Cf) {
                *(float2*)(Cf + o0) = make_float2(x0, x1);
                *(float2*)(Cf + o1) = make_float2(y0, y1);
            }
            if (Ch) {
                *(bf162*)(Ch + o0) = __floats2bfloat162_rn(x0, x1);
                *(bf162*)(Ch + o1) = __floats2bfloat162_rn(y0, y1);
            }
        }
    }
}

// ---------------- fused flash attention ----------------
// O[t,m,h*96:+96] = softmax_k( Qh.Kh*SCALE - 2||qpos-kpos||^2 ) @ Vh
// 64-row Q tile per CTA (4 warps x 16 rows), 64-key blocks double buffered.
// smem layout (dynamic): sQ[3][64][32] | sK[2][3][64][32] | sV[2][64][104] | sKP[2][64]f2
template<int MQ, int KN, bool QPT, bool KPT>
__global__ __launch_bounds__(128) void flash_h(
    const bf16* __restrict__ Q, const bf16* __restrict__ K,
    const bf16* __restrict__ V, bf16* __restrict__ O,
    const float* __restrict__ qpos, const float* __restrict__ kpos)
{
    constexpr int ITERS = KN / 64;
    extern __shared__ char smem[];
    unsigned qU  = cvta_s(smem);
    unsigned kU  = qU + 12288;
    unsigned vU  = qU + 36864;
    unsigned kpU = qU + 63488;
    float2* sKP = (float2*)(smem + 63488);

    const int z = blockIdx.y, t = z >> 3, h = z & 7;
    const int bm = blockIdx.x * 64;
    const bf16* Qb = Q + (size_t)t * MQ * D_ + h * HD_;
    const bf16* Kb = K + (size_t)t * KN * D_ + h * HD_;
    const bf16* Vb = V + (size_t)t * KN * D_ + h * HD_;
    bf16* Ob = O + (size_t)t * MQ * D_ + h * HD_;
    const float* qp = qpos + (QPT ? (size_t)t * MQ * 2 : 0);
    const float* kp = kpos + (KPT ? (size_t)t * KN * 2 : 0);

    const int tid = threadIdx.x, lane = tid & 31, w = tid >> 5;
    const int gq = lane >> 2, tg = lane & 3;
    const int rlow = lane & 15, khalf = lane >> 4;

    // precomputed load offsets (6 x 16B chunks per thread covering 64x96 bf16)
    int lrow[6], lg[6];
    unsigned kdst[6], vdst[6];
    size_t soff[6];
#pragma unroll
    for (int i = 0; i < 6; i++) {
        int idx = tid + i * 128;
        lrow[i] = idx / 12; lg[i] = idx % 12;
        kdst[i] = ((lg[i] >> 2) * 4096) + (swz(lrow[i], lg[i] & 3) << 1);
        vdst[i] = lrow[i] * 208 + lg[i] * 16;
        soff[i] = (size_t)lrow[i] * D_ + lg[i] * 8;
    }

    // Q tile + block 0 (group 0)
#pragma unroll
    for (int i = 0; i < 6; i++) {
        CP16(qU + kdst[i], Qb + (size_t)bm * D_ + soff[i]);
        CP16(kU + kdst[i], Kb + soff[i]);
        CP16(vU + vdst[i], Vb + soff[i]);
    }
    if (tid < 32) CP16(kpU + tid * 16, (const char*)kp + tid * 16);
    CPC();

    // query coords for this thread's two rows
    float2 q0 = *(const float2*)(qp + 2 * (bm + w * 16 + gq));
    float2 q1 = *(const float2*)(qp + 2 * (bm + w * 16 + gq + 8));

    float m0 = -1e30f, m1 = -1e30f, l0 = 0.0f, l1 = 0.0f;
    float o[12][4] = {};
    unsigned qa[6][4];

    for (int it = 0; it < ITERS; ++it) {
        int buf = it & 1;
        if (it + 1 < ITERS) {
            int kb = (it + 1) * 64;
            unsigned ok = (buf ^ 1) * 12288u, ov = (buf ^ 1) * 13312u;
            size_t sb = (size_t)kb * D_;
#pragma unroll
            for (int i = 0; i < 6; i++) {
                CP16(kU + ok + kdst[i], Kb + sb + soff[i]);
                CP16(vU + ov + vdst[i], Vb + sb + soff[i]);
            }
            if (tid < 32) CP16(kpU + (buf ^ 1) * 512 + tid * 16, (const char*)kp + (size_t)kb * 8 + tid * 16);
            CPC(); CPW(1);
        } else CPW(0);
        __syncthreads();

        if (it == 0) {
#pragma unroll
            for (int ks = 0; ks < 6; ks++) {
                int kc = ks >> 1, g = ((ks & 1) << 1) + khalf;
                ldsm4(qU + kc * 4096 + (swz(w * 16 + rlow, g) << 1),
                      qa[ks][0], qa[ks][1], qa[ks][2], qa[ks][3]);
            }
        }

        unsigned kbase = kU + buf * 12288u, vbase = vU + buf * 13312u;
        float2* kpb = sKP + buf * 64;

        // ---- scores: 16x64 per warp ----
        float s[8][4] = {};
#pragma unroll
        for (int ks = 0; ks < 6; ks++) {
            int kc = ks >> 1, g = ((ks & 1) << 1) + khalf;
            unsigned bfr[4][4];
#pragma unroll
            for (int rg = 0; rg < 4; rg++)
                ldsm4(kbase + kc * 4096 + (swz(rg * 16 + rlow, g) << 1),
                      bfr[rg][0], bfr[rg][1], bfr[rg][2], bfr[rg][3]);
#pragma unroll
            for (int rg = 0; rg < 4; rg++) {
                mma_bf16(s[2 * rg],     qa[ks][0], qa[ks][1], qa[ks][2], qa[ks][3], bfr[rg][0], bfr[rg][2]);
                mma_bf16(s[2 * rg + 1], qa[ks][0], qa[ks][1], qa[ks][2], qa[ks][3], bfr[rg][1], bfr[rg][3]);
            }
        }

        // ---- bias + scale, row max ----
        float rm0 = -1e30f, rm1 = -1e30f;
#pragma unroll
        for (int j = 0; j < 8; j++) {
            float2 kp0 = kpb[8 * j + 2 * tg];
            float2 kp1 = kpb[8 * j + 2 * tg + 1];
            float dx, dy;
            dx = q0.x - kp0.x; dy = q0.y - kp0.y;
            s[j][0] = s[j][0] * SCALE_F - 2.0f * (dx * dx + dy * dy);
            dx = q0.x - kp1.x; dy = q0.y - kp1.y;
            s[j][1] = s[j][1] * SCALE_F - 2.0f * (dx * dx + dy * dy);
            dx = q1.x - kp0.x; dy = q1.y - kp0.y;
            s[j][2] = s[j][2] * SCALE_F - 2.0f * (dx * dx + dy * dy);
            dx = q1.x - kp1.x; dy = q1.y - kp1.y;
            s[j][3] = s[j][3] * SCALE_F - 2.0f * (dx * dx + dy * dy);
            rm0 = fmaxf(rm0, fmaxf(s[j][0], s[j][1]));
            rm1 = fmaxf(rm1, fmaxf(s[j][2], s[j][3]));
        }
        rm0 = fmaxf(rm0, __shfl_xor_sync(~0u, rm0, 1));
        rm0 = fmaxf(rm0, __shfl_xor_sync(~0u, rm0, 2));
        rm1 = fmaxf(rm1, __shfl_xor_sync(~0u, rm1, 1));
        rm1 = fmaxf(rm1, __shfl_xor_sync(~0u, rm1, 2));

        float m0n = fmaxf(m0, rm0), m1n = fmaxf(m1, rm1);
        float sc0 = __expf(m0 - m0n), sc1 = __expf(m1 - m1n);
        m0 = m0n; m1 = m1n;
        l0 *= sc0; l1 *= sc1;
#pragma unroll
        for (int j = 0; j < 8; j++) {
            s[j][0] = __expf(s[j][0] - m0n);
            s[j][1] = __expf(s[j][1] - m0n);
            s[j][2] = __expf(s[j][2] - m1n);
            s[j][3] = __expf(s[j][3] - m1n);
            l0 += s[j][0] + s[j][1];
            l1 += s[j][2] + s[j][3];
        }
#pragma unroll
        for (int nt = 0; nt < 12; nt++) {
            o[nt][0] *= sc0; o[nt][1] *= sc0;
            o[nt][2] *= sc1; o[nt][3] *= sc1;
        }

        // ---- pack P into A fragments (k = 64 keys, 4 k-steps) ----
        unsigned pa[4][4];
#pragma unroll
        for (int kk = 0; kk < 4; kk++) {
            pa[kk][0] = packbf(s[2 * kk][0],     s[2 * kk][1]);
            pa[kk][1] = packbf(s[2 * kk][2],     s[2 * kk][3]);
            pa[kk][2] = packbf(s[2 * kk + 1][0], s[2 * kk + 1][1]);
            pa[kk][3] = packbf(s[2 * kk + 1][2], s[2 * kk + 1][3]);
        }

        // ---- P @ V ----
#pragma unroll
        for (int kk = 0; kk < 4; kk++) {
#pragma unroll
            for (int p = 0; p < 6; p++) {
                unsigned baddr = vbase + (kk * 16 + rlow) * 208 + (p * 16 + khalf * 8) * 2;
                unsigned b0, b1, b2, b3;
                ldsm4t(baddr, b0, b1, b2, b3);
                mma_bf16(o[2 * p],     pa[kk][0], pa[kk][1], pa[kk][2], pa[kk][3], b0, b1);
                mma_bf16(o[2 * p + 1], pa[kk][0], pa[kk][1], pa[kk][2], pa[kk][3], b2, b3);
            }
        }
        __syncthreads();
    }

    l0 += __shfl_xor_sync(~0u, l0, 1); l0 += __shfl_xor_sync(~0u, l0, 2);
    l1 += __shfl_xor_sync(~0u, l1, 1); l1 += __shfl_xor_sync(~0u, l1, 2);
    float inv0 = 1.0f / l0, inv1 = 1.0f / l1;

    int mrow = bm + w * 16 + gq;
#pragma unroll
    for (int nt = 0; nt < 12; nt++) {
        int n0 = nt * 8 + 2 * tg;
        *(bf162*)(Ob + (size_t)mrow * D_ + n0) =
            __floats2bfloat162_rn(o[nt][0] * inv0, o[nt][1] * inv0);
        *(bf162*)(Ob + (size_t)(mrow + 8) * D_ + n0) =
            __floats2bfloat162_rn(o[nt][2] * inv1, o[nt][3] * inv1);
    }
}

// =================================================================================
extern "C" void kernel_launch(void* const* d_in, const int* in_sizes, int n_in,
                              void* d_out, int out_size)
{
    const float* features = (const float*)d_in[0];
    const float* tracks   = (const float*)d_in[1];
    const float* fpos     = (const float*)d_in[2];
    const float* tpe      = (const float*)d_in[3];
    const float* fpe      = (const float*)d_in[4];
    WP wp;
    wp.p[0] = (const float*)d_in[5];   // Wq_s
    wp.p[1] = (const float*)d_in[6];   // Wk_s
    wp.p[2] = (const float*)d_in[7];   // Wv_s
    wp.p[3] = (const float*)d_in[10];  // Wo_s
    wp.p[4] = (const float*)d_in[11];  // Wq_p
    wp.p[5] = (const float*)d_in[12];  // Wk_p
    wp.p[6] = (const float*)d_in[13];  // Wv_p
    wp.p[7] = (const float*)d_in[16];  // Wout_p
    const float* qg_s = (const float*)d_in[8];
    const float* kg_s = (const float*)d_in[9];
    const float* qg_p = (const float*)d_in[14];
    const float* kg_p = (const float*)d_in[15];
    float* out = (float*)d_out;

    bf16 *feat_h, *fp_h, *fpe_h, *kb_h, *vb_h, *big0_h, *tpe_h, *qb_h, *sh_h, *samp_h, *sm0_h, *w_h;
    cudaGetSymbolAddress((void**)&feat_h, h_feat);
    cudaGetSymbolAddress((void**)&fp_h,   h_fp);
    cudaGetSymbolAddress((void**)&fpe_h,  h_fpe);
    cudaGetSymbolAddress((void**)&kb_h,   h_kb);
    cudaGetSymbolAddress((void**)&vb_h,   h_vb);
    cudaGetSymbolAddress((void**)&big0_h, h_big0);
    cudaGetSymbolAddress((void**)&tpe_h,  h_tpe);
    cudaGetSymbolAddress((void**)&qb_h,   h_qb);
    cudaGetSymbolAddress((void**)&sh_h,   h_sh);
    cudaGetSymbolAddress((void**)&samp_h, h_samp);
    cudaGetSymbolAddress((void**)&sm0_h,  h_sm0);
    cudaGetSymbolAddress((void**)&w_h,    h_W);

    const int NBIG = T_ * HW_ * D_;  // 12,582,912
    const int NSM  = T_ * M_ * D_;   // 3,145,728
    const int NW   = D_ * D_;        // 589,824

    const int FSMEM = 64512;
    cudaFuncSetAttribute(flash_h<M_, HW_, true, false>,
                         cudaFuncAttributeMaxDynamicSharedMemorySize, FSMEM);
    cudaFuncSetAttribute(flash_h<HW_, M_, false, true>,
                         cudaFuncAttributeMaxDynamicSharedMemorySize, FSMEM);

    // conversions
    cvt3<<<NBIG / 1024, 256>>>(features, fpe, feat_h, fpe_h, fp_h, NBIG / 4);
    cvt4<<<NSM / 1024, 256>>>(tpe, tpe_h, NSM / 4);
    cvtw<<<dim3(NW / 1024, 8), 256>>>(wp, w_h);

    dim3 gBig(6, 128);   // 768/128 x 16384/128
    dim3 gSm(6, 32);

    // ---- sampling ----
    gemm_h<<<gBig, 256>>>(fp_h, w_h + 1 * (size_t)NW, nullptr, nullptr, big0_h);   // K pre-LN
    ln_bh<<<T_ * HW_, 256>>>(big0_h, kg_s, kb_h);
    gemm_h<<<gBig, 256>>>(feat_h, w_h + 2 * (size_t)NW, nullptr, nullptr, vb_h);   // V
    gemm_h<<<gSm, 256>>>(tpe_h, w_h + 0 * (size_t)NW, nullptr, nullptr, sm0_h);    // Q pre-LN
    ln_bh<<<T_ * M_, 256>>>(sm0_h, qg_s, qb_h);

    flash_h<M_, HW_, true, false><<<dim3(M_ / 64, T_ * H_), 128, FSMEM>>>(
        qb_h, kb_h, vb_h, sh_h, tracks, fpos);

    gemm_h<<<gSm, 256>>>(sh_h, w_h + 3 * (size_t)NW, nullptr, nullptr, samp_h);    // sampled

    // ---- splatting ----
    gemm_h<<<gBig, 256>>>(fpe_h, w_h + 4 * (size_t)NW, nullptr, nullptr, big0_h);  // Q2 pre-LN
    ln_bh<<<T_ * HW_, 256>>>(big0_h, qg_p, fp_h);
    gemm_h<<<gSm, 256>>>(tpe_h, w_h + 5 * (size_t)NW, nullptr, nullptr, sm0_h);    // K2 pre-LN
    ln_bh<<<T_ * M_, 256>>>(sm0_h, kg_p, qb_h);
    gemm_h<<<gSm, 256>>>(samp_h, w_h + 6 * (size_t)NW, nullptr, nullptr, sh_h);    // V2

    flash_h<HW_, M_, false, true><<<dim3(HW_ / 64, T_ * H_), 128, FSMEM>>>(
        fp_h, qb_h, sh_h, kb_h, fpos, tracks);

    // out = features + upd @ Wout^T
    gemm_h<<<gBig, 256>>>(kb_h, w_h + 7 * (size_t)NW, features, out, nullptr);
}

// round 5
// speedup vs baseline: 9.5093x; 1.1218x over previous
#include <cuda_runtime.h>
#include <cuda_bf16.h>
#include <math.h>

#define T_ 16
#define HW_ 1024
#define M_ 256
#define D_ 768
#define H_ 8
#define HD_ 96
#define SCALE_F 0.1020620726159658f  /* 1/sqrt(96) */

typedef __nv_bfloat16 bf16;
typedef __nv_bfloat162 bf162;

// ---------------- scratch (static device globals; no allocation) ----------------
__device__ __align__(256) bf16 h_feat[(size_t)T_ * HW_ * D_];
__device__ __align__(256) bf16 h_fp  [(size_t)T_ * HW_ * D_];   // featplus / Q2_ln
__device__ __align__(256) bf16 h_fpe [(size_t)T_ * HW_ * D_];
__device__ __align__(256) bf16 h_kb  [(size_t)T_ * HW_ * D_];   // K_ln / upd
__device__ __align__(256) bf16 h_vb  [(size_t)T_ * HW_ * D_];   // V
__device__ __align__(256) bf16 h_big0[(size_t)T_ * HW_ * D_];   // pre-LN scratch (big)
__device__ __align__(256) bf16 h_tpe [(size_t)T_ * M_ * D_];
__device__ __align__(256) bf16 h_qb  [(size_t)T_ * M_ * D_];    // Q_ln / K2_ln
__device__ __align__(256) bf16 h_sh  [(size_t)T_ * M_ * D_];    // sampled-heads / V2
__device__ __align__(256) bf16 h_samp[(size_t)T_ * M_ * D_];
__device__ __align__(256) bf16 h_sm0 [(size_t)T_ * M_ * D_];    // pre-LN scratch (small)
__device__ __align__(256) bf16 h_W[8][D_ * D_];

// ---------------- ptx helpers ----------------
__device__ __forceinline__ unsigned cvta_s(const void* p) {
    return (unsigned)__cvta_generic_to_shared(p);
}
#define CP16(dst, src) asm volatile("cp.async.cg.shared.global [%0], [%1], 16;" :: "r"(dst), "l"(src))
#define CPC() asm volatile("cp.async.commit_group;")
#define CPW(n) asm volatile("cp.async.wait_group %0;" :: "n"(n))

__device__ __forceinline__ void ldsm4(unsigned a, unsigned& r0, unsigned& r1, unsigned& r2, unsigned& r3) {
    asm volatile("ldmatrix.sync.aligned.m8n8.x4.shared.b16 {%0,%1,%2,%3}, [%4];"
                 : "=r"(r0), "=r"(r1), "=r"(r2), "=r"(r3) : "r"(a));
}
__device__ __forceinline__ void ldsm4t(unsigned a, unsigned& r0, unsigned& r1, unsigned& r2, unsigned& r3) {
    asm volatile("ldmatrix.sync.aligned.m8n8.x4.trans.shared.b16 {%0,%1,%2,%3}, [%4];"
                 : "=r"(r0), "=r"(r1), "=r"(r2), "=r"(r3) : "r"(a));
}
__device__ __forceinline__ void mma_bf16(float* c,
    unsigned a0, unsigned a1, unsigned a2, unsigned a3, unsigned b0, unsigned b1) {
    asm volatile(
        "mma.sync.aligned.m16n8k16.row.col.f32.bf16.bf16.f32 "
        "{%0,%1,%2,%3},{%4,%5,%6,%7},{%8,%9},{%0,%1,%2,%3};"
        : "+f"(c[0]), "+f"(c[1]), "+f"(c[2]), "+f"(c[3])
        : "r"(a0), "r"(a1), "r"(a2), "r"(a3), "r"(b0), "r"(b1));
}
__device__ __forceinline__ unsigned packbf(float x, float y) {
    bf162 v = __floats2bfloat162_rn(x, y);
    return *reinterpret_cast<unsigned*>(&v);
}
// swizzled bf16-unit offset in a [rows][32] bf16 tile
__device__ __forceinline__ unsigned swz(int row, int g) {
    return ((row >> 1) << 6) | (((((row & 1) << 2) | g) ^ ((row >> 1) & 7)) << 3);
}

// ---------------- conversions ----------------
__global__ __launch_bounds__(256) void cvt3(const float* __restrict__ f, const float* __restrict__ pe,
                                            bf16* __restrict__ feat, bf16* __restrict__ fpeh,
                                            bf16* __restrict__ fph, int n4) {
    int i = blockIdx.x * 256 + threadIdx.x;
    if (i < n4) {
        float4 x = ((const float4*)f)[i];
        float4 y = ((const float4*)pe)[i];
        ((bf162*)feat)[2 * i]     = __floats2bfloat162_rn(x.x, x.y);
        ((bf162*)feat)[2 * i + 1] = __floats2bfloat162_rn(x.z, x.w);
        ((bf162*)fpeh)[2 * i]     = __floats2bfloat162_rn(y.x, y.y);
        ((bf162*)fpeh)[2 * i + 1] = __floats2bfloat162_rn(y.z, y.w);
        ((bf162*)fph)[2 * i]      = __floats2bfloat162_rn(x.x + y.x, x.y + y.y);
        ((bf162*)fph)[2 * i + 1]  = __floats2bfloat162_rn(x.z + y.z, x.w + y.w);
    }
}
__global__ __launch_bounds__(256) void cvt4(const float* __restrict__ s, bf16* __restrict__ d, int n4) {
    int i = blockIdx.x * 256 + threadIdx.x;
    if (i < n4) {
        float4 v = ((const float4*)s)[i];
        ((bf162*)d)[2 * i]     = __floats2bfloat162_rn(v.x, v.y);
        ((bf162*)d)[2 * i + 1] = __floats2bfloat162_rn(v.z, v.w);
    }
}
struct WP { const float* p[8]; };
__global__ __launch_bounds__(256) void cvtw(WP wp, bf16* __restrict__ dst) {
    int wi = blockIdx.y;
    const float* s = wp.p[wi];
    bf16* d = dst + (size_t)wi * (D_ * D_);
    int i = blockIdx.x * 256 + threadIdx.x;   // n4 = D_*D_/4
    float4 v = ((const float4*)s)[i];
    ((bf162*)d)[2 * i]     = __floats2bfloat162_rn(v.x, v.y);
    ((bf162*)d)[2 * i + 1] = __floats2bfloat162_rn(v.z, v.w);
}

// ---------------- LayerNorm: bf16 in -> bf16 out (warp-shuffle reduction) --------
__global__ __launch_bounds__(256) void ln_bh(const bf16* __restrict__ X,
                                             const float* __restrict__ g, bf16* __restrict__ Y) {
    const bf16* row = X + (size_t)blockIdx.x * D_;
    bf16* orow = Y + (size_t)blockIdx.x * D_;
    int tid = threadIdx.x, lane = tid & 31, w = tid >> 5;
    float v0 = __bfloat162float(row[tid]);
    float v1 = __bfloat162float(row[tid + 256]);
    float v2 = __bfloat162float(row[tid + 512]);
    float s = v0 + v1 + v2;
    float q = v0 * v0 + v1 * v1 + v2 * v2;
#pragma unroll
    for (int o = 16; o; o >>= 1) {
        s += __shfl_xor_sync(~0u, s, o);
        q += __shfl_xor_sync(~0u, q, o);
    }
    __shared__ float ps[8], pq[8], bc[2];
    if (lane == 0) { ps[w] = s; pq[w] = q; }
    __syncthreads();
    if (tid == 0) {
        float ts = 0.0f, tq = 0.0f;
#pragma unroll
        for (int i = 0; i < 8; i++) { ts += ps[i]; tq += pq[i]; }
        float mean = ts * (1.0f / 768.0f);
        float var = tq * (1.0f / 768.0f) - mean * mean;
        bc[0] = mean;
        bc[1] = rsqrtf(var + 1e-6f);
    }
    __syncthreads();
    float mean = bc[0], inv = bc[1];
    orow[tid]       = __float2bfloat16((v0 - mean) * inv * g[tid]);
    orow[tid + 256] = __float2bfloat16((v1 - mean) * inv * g[tid + 256]);
    orow[tid + 512] = __float2bfloat16((v2 - mean) * inv * g[tid + 512]);
}

// ---------------- dense GEMM: C[R,768] = A[R,768] @ W[768,768]^T ----------------
// 3-stage cp.async pipeline, one barrier per k-step. Dynamic smem 48KB.
__global__ __launch_bounds__(256) void gemm_h(
    const bf16* __restrict__ A, const bf16* __restrict__ W,
    const float* __restrict__ addsrc, float* __restrict__ Cf, bf16* __restrict__ Ch)
{
    extern __shared__ bf16 sm[];          // 3 stages x (A 8KB | W 8KB)
    const int tid = threadIdx.x, lane = tid & 31, warp = tid >> 5;
    const int wm = warp & 3, wn = warp >> 2;
    const int bm = blockIdx.y * 128, bn = blockIdx.x * 128;
    const unsigned base = cvta_s(sm);
    const int r0 = tid >> 2, r1 = r0 + 64, gg = tid & 3;
    const bf16* As0 = A + (size_t)(bm + r0) * D_ + gg * 8;
    const bf16* As1 = A + (size_t)(bm + r1) * D_ + gg * 8;
    const bf16* Ws0 = W + (size_t)(bn + r0) * D_ + gg * 8;
    const bf16* Ws1 = W + (size_t)(bn + r1) * D_ + gg * 8;
    const unsigned dA0 = base + (swz(r0, gg) << 1), dA1 = base + (swz(r1, gg) << 1);
    const unsigned dW0 = base + 8192 + (swz(r0, gg) << 1), dW1 = base + 8192 + (swz(r1, gg) << 1);

    float c[2][8][4] = {};

    // prologue: stages 0,1
#pragma unroll
    for (int s = 0; s < 2; s++) {
        unsigned o = s * 16384u;
        int k0 = s * 32;
        CP16(dA0 + o, As0 + k0); CP16(dA1 + o, As1 + k0);
        CP16(dW0 + o, Ws0 + k0); CP16(dW1 + o, Ws1 + k0);
        CPC();
    }

    const int ITERS = D_ / 32;  // 24
    const int rlow = lane & 15, khalf = lane >> 4;
    for (int it = 0; it < ITERS; ++it) {
        CPW(1);
        __syncthreads();
        if (it + 2 < ITERS) {
            int k0 = (it + 2) * 32;
            unsigned o = (unsigned)((it + 2) % 3) * 16384u;
            CP16(dA0 + o, As0 + k0); CP16(dA1 + o, As1 + k0);
            CP16(dW0 + o, Ws0 + k0); CP16(dW1 + o, Ws1 + k0);
        }
        CPC();
        unsigned so = (unsigned)(it % 3) * 16384u;
        unsigned ab = base + so, wb = base + 8192 + so;
#pragma unroll
        for (int kk = 0; kk < 32; kk += 16) {
            int g = (kk >> 3) + khalf;
            unsigned a[2][4], bfr[4][4];
#pragma unroll
            for (int mt = 0; mt < 2; mt++) {
                int row = wm * 32 + mt * 16 + rlow;
                ldsm4(ab + (swz(row, g) << 1), a[mt][0], a[mt][1], a[mt][2], a[mt][3]);
            }
#pragma unroll
            for (int bt = 0; bt < 4; bt++) {
                int row = wn * 64 + bt * 16 + rlow;
                ldsm4(wb + (swz(row, g) << 1), bfr[bt][0], bfr[bt][1], bfr[bt][2], bfr[bt][3]);
            }
#pragma unroll
            for (int mt = 0; mt < 2; mt++)
#pragma unroll
                for (int nt = 0; nt < 8; nt++) {
                    int bt = nt >> 1, hi = nt & 1;
                    mma_bf16(c[mt][nt], a[mt][0], a[mt][1], a[mt][2], a[mt][3],
                             bfr[bt][hi ? 1 : 0], bfr[bt][hi ? 3 : 2]);
                }
        }
    }

    const int ml = lane >> 2, nl = 2 * (lane & 3);
#pragma unroll
    for (int mt = 0; mt < 2; mt++) {
        int m0 = bm + wm * 32 + mt * 16 + ml;
#pragma unroll
        for (int nt = 0; nt < 8; nt++) {
            int n0 = bn + wn * 64 + nt * 8 + nl;
            size_t o0 = (size_t)m0 * D_ + n0, o1 = o0 + (size_t)8 * D_;
            float x0 = c[mt][nt][0], x1 = c[mt][nt][1];
            float y0 = c[mt][nt][2], y1 = c[mt][nt][3];
            if (addsrc) {
                float2 s0 = *(const float2*)(addsrc + o0);
                float2 s1 = *(const float2*)(addsrc + o1);
                x0 += s0.x; x1 += s0.y; y0 += s1.x; y1 += s1.y;
            }
            if (Cf) {
                *(float2*)(Cf + o0) = make_float2(x0, x1);
                *(float2*)(Cf + o1) = make_float2(y0, y1);
            }
            if (Ch) {
                *(bf162*)(Ch + o0) = __floats2bfloat162_rn(x0, x1);
                *(bf162*)(Ch + o1) = __floats2bfloat162_rn(y0, y1);
            }
        }
    }
}

// ---------------- fused flash attention ----------------
// O[t,m,h*96:+96] = softmax_k( Qh.Kh*SCALE - 2||qpos-kpos||^2 ) @ Vh
template<int MQ, int KN, bool QPT, bool KPT>
__global__ __launch_bounds__(128) void flash_h(
    const bf16* __restrict__ Q, const bf16* __restrict__ K,
    const bf16* __restrict__ V, bf16* __restrict__ O,
    const float* __restrict__ qpos, const float* __restrict__ kpos)
{
    constexpr int ITERS = KN / 64;
    extern __shared__ char smem[];
    unsigned qU  = cvta_s(smem);
    unsigned kU  = qU + 12288;
    unsigned vU  = qU + 36864;
    unsigned kpU = qU + 63488;
    float2* sKP = (float2*)(smem + 63488);

    const int z = blockIdx.y, t = z >> 3, h = z & 7;
    const int bm = blockIdx.x * 64;
    const bf16* Qb = Q + (size_t)t * MQ * D_ + h * HD_;
    const bf16* Kb = K + (size_t)t * KN * D_ + h * HD_;
    const bf16* Vb = V + (size_t)t * KN * D_ + h * HD_;
    bf16* Ob = O + (size_t)t * MQ * D_ + h * HD_;
    const float* qp = qpos + (QPT ? (size_t)t * MQ * 2 : 0);
    const float* kp = kpos + (KPT ? (size_t)t * KN * 2 : 0);

    const int tid = threadIdx.x, lane = tid & 31, w = tid >> 5;
    const int gq = lane >> 2, tg = lane & 3;
    const int rlow = lane & 15, khalf = lane >> 4;

    int lrow[6], lg[6];
    unsigned kdst[6], vdst[6];
    size_t soff[6];
#pragma unroll
    for (int i = 0; i < 6; i++) {
        int idx = tid + i * 128;
        lrow[i] = idx / 12; lg[i] = idx % 12;
        kdst[i] = ((lg[i] >> 2) * 4096) + (swz(lrow[i], lg[i] & 3) << 1);
        vdst[i] = lrow[i] * 208 + lg[i] * 16;
        soff[i] = (size_t)lrow[i] * D_ + lg[i] * 8;
    }

#pragma unroll
    for (int i = 0; i < 6; i++) {
        CP16(qU + kdst[i], Qb + (size_t)bm * D_ + soff[i]);
        CP16(kU + kdst[i], Kb + soff[i]);
        CP16(vU + vdst[i], Vb + soff[i]);
    }
    if (tid < 32) CP16(kpU + tid * 16, (const char*)kp + tid * 16);
    CPC();

    float2 q0 = *(const float2*)(qp + 2 * (bm + w * 16 + gq));
    float2 q1 = *(const float2*)(qp + 2 * (bm + w * 16 + gq + 8));

    float m0 = -1e30f, m1 = -1e30f, l0 = 0.0f, l1 = 0.0f;
    float o[12][4] = {};
    unsigned qa[6][4];

    for (int it = 0; it < ITERS; ++it) {
        int buf = it & 1;
        if (it + 1 < ITERS) {
            int kb = (it + 1) * 64;
            unsigned ok = (buf ^ 1) * 12288u, ov = (buf ^ 1) * 13312u;
            size_t sb = (size_t)kb * D_;
#pragma unroll
            for (int i = 0; i < 6; i++) {
                CP16(kU + ok + kdst[i], Kb + sb + soff[i]);
                CP16(vU + ov + vdst[i], Vb + sb + soff[i]);
            }
            if (tid < 32) CP16(kpU + (buf ^ 1) * 512 + tid * 16, (const char*)kp + (size_t)kb * 8 + tid * 16);
            CPC(); CPW(1);
        } else CPW(0);
        __syncthreads();

        if (it == 0) {
#pragma unroll
            for (int ks = 0; ks < 6; ks++) {
                int kc = ks >> 1, g = ((ks & 1) << 1) + khalf;
                ldsm4(qU + kc * 4096 + (swz(w * 16 + rlow, g) << 1),
                      qa[ks][0], qa[ks][1], qa[ks][2], qa[ks][3]);
            }
        }

        unsigned kbase = kU + buf * 12288u, vbase = vU + buf * 13312u;
        float2* kpb = sKP + buf * 64;

        float s[8][4] = {};
#pragma unroll
        for (int ks = 0; ks < 6; ks++) {
            int kc = ks >> 1, g = ((ks & 1) << 1) + khalf;
            unsigned bfr[4][4];
#pragma unroll
            for (int rg = 0; rg < 4; rg++)
                ldsm4(kbase + kc * 4096 + (swz(rg * 16 + rlow, g) << 1),
                      bfr[rg][0], bfr[rg][1], bfr[rg][2], bfr[rg][3]);
#pragma unroll
            for (int rg = 0; rg < 4; rg++) {
                mma_bf16(s[2 * rg],     qa[ks][0], qa[ks][1], qa[ks][2], qa[ks][3], bfr[rg][0], bfr[rg][2]);
                mma_bf16(s[2 * rg + 1], qa[ks][0], qa[ks][1], qa[ks][2], qa[ks][3], bfr[rg][1], bfr[rg][3]);
            }
        }

        float rm0 = -1e30f, rm1 = -1e30f;
#pragma unroll
        for (int j = 0; j < 8; j++) {
            float2 kp0 = kpb[8 * j + 2 * tg];
            float2 kp1 = kpb[8 * j + 2 * tg + 1];
            float dx, dy;
            dx = q0.x - kp0.x; dy = q0.y - kp0.y;
            s[j][0] = s[j][0] * SCALE_F - 2.0f * (dx * dx + dy * dy);
            dx = q0.x - kp1.x; dy = q0.y - kp1.y;
            s[j][1] = s[j][1] * SCALE_F - 2.0f * (dx * dx + dy * dy);
            dx = q1.x - kp0.x; dy = q1.y - kp0.y;
            s[j][2] = s[j][2] * SCALE_F - 2.0f * (dx * dx + dy * dy);
            dx = q1.x - kp1.x; dy = q1.y - kp1.y;
            s[j][3] = s[j][3] * SCALE_F - 2.0f * (dx * dx + dy * dy);
            rm0 = fmaxf(rm0, fmaxf(s[j][0], s[j][1]));
            rm1 = fmaxf(rm1, fmaxf(s[j][2], s[j][3]));
        }
        rm0 = fmaxf(rm0, __shfl_xor_sync(~0u, rm0, 1));
        rm0 = fmaxf(rm0, __shfl_xor_sync(~0u, rm0, 2));
        rm1 = fmaxf(rm1, __shfl_xor_sync(~0u, rm1, 1));
        rm1 = fmaxf(rm1, __shfl_xor_sync(~0u, rm1, 2));

        float m0n = fmaxf(m0, rm0), m1n = fmaxf(m1, rm1);
        float sc0 = __expf(m0 - m0n), sc1 = __expf(m1 - m1n);
        m0 = m0n; m1 = m1n;
        l0 *= sc0; l1 *= sc1;
#pragma unroll
        for (int j = 0; j < 8; j++) {
            s[j][0] = __expf(s[j][0] - m0n);
            s[j][1] = __expf(s[j][1] - m0n);
            s[j][2] = __expf(s[j][2] - m1n);
            s[j][3] = __expf(s[j][3] - m1n);
            l0 += s[j][0] + s[j][1];
            l1 += s[j][2] + s[j][3];
        }
#pragma unroll
        for (int nt = 0; nt < 12; nt++) {
            o[nt][0] *= sc0; o[nt][1] *= sc0;
            o[nt][2] *= sc1; o[nt][3] *= sc1;
        }

        unsigned pa[4][4];
#pragma unroll
        for (int kk = 0; kk < 4; kk++) {
            pa[kk][0] = packbf(s[2 * kk][0],     s[2 * kk][1]);
            pa[kk][1] = packbf(s[2 * kk][2],     s[2 * kk][3]);
            pa[kk][2] = packbf(s[2 * kk + 1][0], s[2 * kk + 1][1]);
            pa[kk][3] = packbf(s[2 * kk + 1][2], s[2 * kk + 1][3]);
        }

#pragma unroll
        for (int kk = 0; kk < 4; kk++) {
#pragma unroll
            for (int p = 0; p < 6; p++) {
                unsigned baddr = vbase + (kk * 16 + rlow) * 208 + (p * 16 + khalf * 8) * 2;
                unsigned b0, b1, b2, b3;
                ldsm4t(baddr, b0, b1, b2, b3);
                mma_bf16(o[2 * p],     pa[kk][0], pa[kk][1], pa[kk][2], pa[kk][3], b0, b1);
                mma_bf16(o[2 * p + 1], pa[kk][0], pa[kk][1], pa[kk][2], pa[kk][3], b2, b3);
            }
        }
        __syncthreads();
    }

    l0 += __shfl_xor_sync(~0u, l0, 1); l0 += __shfl_xor_sync(~0u, l0, 2);
    l1 += __shfl_xor_sync(~0u, l1, 1); l1 += __shfl_xor_sync(~0u, l1, 2);
    float inv0 = 1.0f / l0, inv1 = 1.0f / l1;

    int mrow = bm + w * 16 + gq;
#pragma unroll
    for (int nt = 0; nt < 12; nt++) {
        int n0 = nt * 8 + 2 * tg;
        *(bf162*)(Ob + (size_t)mrow * D_ + n0) =
            __floats2bfloat162_rn(o[nt][0] * inv0, o[nt][1] * inv0);
        *(bf162*)(Ob + (size_t)(mrow + 8) * D_ + n0) =
            __floats2bfloat162_rn(o[nt][2] * inv1, o[nt][3] * inv1);
    }
}

// =================================================================================
extern "C" void kernel_launch(void* const* d_in, const int* in_sizes, int n_in,
                              void* d_out, int out_size)
{
    const float* features = (const float*)d_in[0];
    const float* tracks   = (const float*)d_in[1];
    const float* fpos     = (const float*)d_in[2];
    const float* tpe      = (const float*)d_in[3];
    const float* fpe      = (const float*)d_in[4];
    WP wp;
    wp.p[0] = (const float*)d_in[5];   // Wq_s
    wp.p[1] = (const float*)d_in[6];   // Wk_s
    wp.p[2] = (const float*)d_in[7];   // Wv_s
    wp.p[3] = (const float*)d_in[10];  // Wo_s
    wp.p[4] = (const float*)d_in[11];  // Wq_p
    wp.p[5] = (const float*)d_in[12];  // Wk_p
    wp.p[6] = (const float*)d_in[13];  // Wv_p
    wp.p[7] = (const float*)d_in[16];  // Wout_p
    const float* qg_s = (const float*)d_in[8];
    const float* kg_s = (const float*)d_in[9];
    const float* qg_p = (const float*)d_in[14];
    const float* kg_p = (const float*)d_in[15];
    float* out = (float*)d_out;

    bf16 *feat_h, *fp_h, *fpe_h, *kb_h, *vb_h, *big0_h, *tpe_h, *qb_h, *sh_h, *samp_h, *sm0_h, *w_h;
    cudaGetSymbolAddress((void**)&feat_h, h_feat);
    cudaGetSymbolAddress((void**)&fp_h,   h_fp);
    cudaGetSymbolAddress((void**)&fpe_h,  h_fpe);
    cudaGetSymbolAddress((void**)&kb_h,   h_kb);
    cudaGetSymbolAddress((void**)&vb_h,   h_vb);
    cudaGetSymbolAddress((void**)&big0_h, h_big0);
    cudaGetSymbolAddress((void**)&tpe_h,  h_tpe);
    cudaGetSymbolAddress((void**)&qb_h,   h_qb);
    cudaGetSymbolAddress((void**)&sh_h,   h_sh);
    cudaGetSymbolAddress((void**)&samp_h, h_samp);
    cudaGetSymbolAddress((void**)&sm0_h,  h_sm0);
    cudaGetSymbolAddress((void**)&w_h,    h_W);

    const int NBIG = T_ * HW_ * D_;  // 12,582,912
    const int NSM  = T_ * M_ * D_;   // 3,145,728
    const int NW   = D_ * D_;        // 589,824

    const int GSMEM = 49152;   // 3 stages x 16KB
    cudaFuncSetAttribute(gemm_h, cudaFuncAttributeMaxDynamicSharedMemorySize, GSMEM);
    const int FSMEM = 64512;
    cudaFuncSetAttribute(flash_h<M_, HW_, true, false>,
                         cudaFuncAttributeMaxDynamicSharedMemorySize, FSMEM);
    cudaFuncSetAttribute(flash_h<HW_, M_, false, true>,
                         cudaFuncAttributeMaxDynamicSharedMemorySize, FSMEM);

    // conversions
    cvt3<<<NBIG / 1024, 256>>>(features, fpe, feat_h, fpe_h, fp_h, NBIG / 4);
    cvt4<<<NSM / 1024, 256>>>(tpe, tpe_h, NSM / 4);
    cvtw<<<dim3(NW / 1024, 8), 256>>>(wp, w_h);

    dim3 gBig(6, 128);   // 768/128 x 16384/128
    dim3 gSm(6, 32);

    // ---- sampling ----
    gemm_h<<<gBig, 256, GSMEM>>>(fp_h, w_h + 1 * (size_t)NW, nullptr, nullptr, big0_h);   // K pre-LN
    ln_bh<<<T_ * HW_, 256>>>(big0_h, kg_s, kb_h);
    gemm_h<<<gBig, 256, GSMEM>>>(feat_h, w_h + 2 * (size_t)NW, nullptr, nullptr, vb_h);   // V
    gemm_h<<<gSm, 256, GSMEM>>>(tpe_h, w_h + 0 * (size_t)NW, nullptr, nullptr, sm0_h);    // Q pre-LN
    ln_bh<<<T_ * M_, 256>>>(sm0_h, qg_s, qb_h);

    flash_h<M_, HW_, true, false><<<dim3(M_ / 64, T_ * H_), 128, FSMEM>>>(
        qb_h, kb_h, vb_h, sh_h, tracks, fpos);

    gemm_h<<<gSm, 256, GSMEM>>>(sh_h, w_h + 3 * (size_t)NW, nullptr, nullptr, samp_h);    // sampled

    // ---- splatting ----
    gemm_h<<<gBig, 256, GSMEM>>>(fpe_h, w_h + 4 * (size_t)NW, nullptr, nullptr, big0_h);  // Q2 pre-LN
    ln_bh<<<T_ * HW_, 256>>>(big0_h, qg_p, fp_h);
    gemm_h<<<gSm, 256, GSMEM>>>(tpe_h, w_h + 5 * (size_t)NW, nullptr, nullptr, sm0_h);    // K2 pre-LN
    ln_bh<<<T_ * M_, 256>>>(sm0_h, kg_p, qb_h);
    gemm_h<<<gSm, 256, GSMEM>>>(samp_h, w_h + 6 * (size_t)NW, nullptr, nullptr, sh_h);    // V2

    flash_h<HW_, M_, false, true><<<dim3(HW_ / 64, T_ * H_), 128, FSMEM>>>(
        fp_h, qb_h, sh_h, kb_h, fpos, tracks);

    // out = features + upd @ Wout^T
    gemm_h<<<gBig, 256, GSMEM>>>(kb_h, w_h + 7 * (size_t)NW, features, out, nullptr);
}

// round 8
// speedup vs baseline: 10.9163x; 1.1480x over previous
#include <cuda_runtime.h>
#include <cuda_bf16.h>
#include <math.h>
#include <stdint.h>

#define T_ 16
#define HW_ 1024
#define M_ 256
#define D_ 768
#define H_ 8
#define HD_ 96
#define SCALE_F 0.1020620726159658f  /* 1/sqrt(96) */

typedef __nv_bfloat16 bf16;
typedef __nv_bfloat162 bf162;

// ---------------- scratch (static device globals; no allocation) ----------------
__device__ __align__(256) bf16 h_feat[(size_t)T_ * HW_ * D_];
__device__ __align__(256) bf16 h_fp  [(size_t)T_ * HW_ * D_];   // featplus
__device__ __align__(256) bf16 h_fpe [(size_t)T_ * HW_ * D_];
__device__ __align__(256) bf16 h_kb  [(size_t)T_ * HW_ * D_];   // K_ln
__device__ __align__(256) bf16 h_vb  [(size_t)T_ * HW_ * D_];   // V
__device__ __align__(256) bf16 h_big0[(size_t)T_ * HW_ * D_];   // K pre-LN
__device__ __align__(256) bf16 h_big1[(size_t)T_ * HW_ * D_];   // Q2 pre-LN
__device__ __align__(256) bf16 h_q2  [(size_t)T_ * HW_ * D_];   // Q2_ln
__device__ __align__(256) bf16 h_upd [(size_t)T_ * HW_ * D_];   // flash2 out
__device__ __align__(256) bf16 h_tpe [(size_t)T_ * M_ * D_];
__device__ __align__(256) bf16 h_qb  [(size_t)T_ * M_ * D_];    // Q_ln
__device__ __align__(256) bf16 h_sm0 [(size_t)T_ * M_ * D_];    // Q pre-LN
__device__ __align__(256) bf16 h_sm1 [(size_t)T_ * M_ * D_];    // K2 pre-LN
__device__ __align__(256) bf16 h_k2  [(size_t)T_ * M_ * D_];    // K2_ln
__device__ __align__(256) bf16 h_sh  [(size_t)T_ * M_ * D_];    // sampled-heads
__device__ __align__(256) bf16 h_samp[(size_t)T_ * M_ * D_];
__device__ __align__(256) bf16 h_v2  [(size_t)T_ * M_ * D_];    // V2
__device__ __align__(256) bf16 h_W[8][D_ * D_];

// ---------------- ptx helpers ----------------
__device__ __forceinline__ unsigned cvta_s(const void* p) {
    return (unsigned)__cvta_generic_to_shared(p);
}
#define CP16(dst, src) asm volatile("cp.async.cg.shared.global [%0], [%1], 16;" :: "r"(dst), "l"(src))
#define CPC() asm volatile("cp.async.commit_group;")
#define CPW(n) asm volatile("cp.async.wait_group %0;" :: "n"(n))

__device__ __forceinline__ void ldsm4(unsigned a, unsigned& r0, unsigned& r1, unsigned& r2, unsigned& r3) {
    asm volatile("ldmatrix.sync.aligned.m8n8.x4.shared.b16 {%0,%1,%2,%3}, [%4];"
                 : "=r"(r0), "=r"(r1), "=r"(r2), "=r"(r3) : "r"(a));
}
__device__ __forceinline__ void ldsm4t(unsigned a, unsigned& r0, unsigned& r1, unsigned& r2, unsigned& r3) {
    asm volatile("ldmatrix.sync.aligned.m8n8.x4.trans.shared.b16 {%0,%1,%2,%3}, [%4];"
                 : "=r"(r0), "=r"(r1), "=r"(r2), "=r"(r3) : "r"(a));
}
__device__ __forceinline__ void mma_bf16(float* c,
    unsigned a0, unsigned a1, unsigned a2, unsigned a3, unsigned b0, unsigned b1) {
    asm volatile(
        "mma.sync.aligned.m16n8k16.row.col.f32.bf16.bf16.f32 "
        "{%0,%1,%2,%3},{%4,%5,%6,%7},{%8,%9},{%0,%1,%2,%3};"
        : "+f"(c[0]), "+f"(c[1]), "+f"(c[2]), "+f"(c[3])
        : "r"(a0), "r"(a1), "r"(a2), "r"(a3), "r"(b0), "r"(b1));
}
__device__ __forceinline__ unsigned packbf(float x, float y) {
    bf162 v = __floats2bfloat162_rn(x, y);
    return *reinterpret_cast<unsigned*>(&v);
}
// swizzled bf16-unit offset in a [rows][32] bf16 tile
__device__ __forceinline__ unsigned swz(int row, int g) {
    return ((row >> 1) << 6) | (((((row & 1) << 2) | g) ^ ((row >> 1) & 7)) << 3);
}

// ---------------- conversions ----------------
__global__ __launch_bounds__(256) void cvt3(const float* __restrict__ f, const float* __restrict__ pe,
                                            bf16* __restrict__ feat, bf16* __restrict__ fpeh,
                                            bf16* __restrict__ fph, int n4) {
    int i = blockIdx.x * 256 + threadIdx.x;
    if (i < n4) {
        float4 x = ((const float4*)f)[i];
        float4 y = ((const float4*)pe)[i];
        ((bf162*)feat)[2 * i]     = __floats2bfloat162_rn(x.x, x.y);
        ((bf162*)feat)[2 * i + 1] = __floats2bfloat162_rn(x.z, x.w);
        ((bf162*)fpeh)[2 * i]     = __floats2bfloat162_rn(y.x, y.y);
        ((bf162*)fpeh)[2 * i + 1] = __floats2bfloat162_rn(y.z, y.w);
        ((bf162*)fph)[2 * i]      = __floats2bfloat162_rn(x.x + y.x, x.y + y.y);
        ((bf162*)fph)[2 * i + 1]  = __floats2bfloat162_rn(x.z + y.z, x.w + y.w);
    }
}
__global__ __launch_bounds__(256) void cvt4(const float* __restrict__ s, bf16* __restrict__ d, int n4) {
    int i = blockIdx.x * 256 + threadIdx.x;
    if (i < n4) {
        float4 v = ((const float4*)s)[i];
        ((bf162*)d)[2 * i]     = __floats2bfloat162_rn(v.x, v.y);
        ((bf162*)d)[2 * i + 1] = __floats2bfloat162_rn(v.z, v.w);
    }
}
struct WP { const float* p[8]; };
__global__ __launch_bounds__(256) void cvtw(WP wp, bf16* __restrict__ dst) {
    int wi = blockIdx.y;
    const float* s = wp.p[wi];
    bf16* d = dst + (size_t)wi * (D_ * D_);
    int i = blockIdx.x * 256 + threadIdx.x;
    float4 v = ((const float4*)s)[i];
    ((bf162*)d)[2 * i]     = __floats2bfloat162_rn(v.x, v.y);
    ((bf162*)d)[2 * i + 1] = __floats2bfloat162_rn(v.z, v.w);
}

// ---------------- LayerNorm: bf16 in -> bf16 out ----------------
__global__ __launch_bounds__(256) void ln_bh(const bf16* __restrict__ X,
                                             const float* __restrict__ g, bf16* __restrict__ Y) {
    const bf16* row = X + (size_t)blockIdx.x * D_;
    bf16* orow = Y + (size_t)blockIdx.x * D_;
    int tid = threadIdx.x, lane = tid & 31, w = tid >> 5;
    float v0 = __bfloat162float(row[tid]);
    float v1 = __bfloat162float(row[tid + 256]);
    float v2 = __bfloat162float(row[tid + 512]);
    float s = v0 + v1 + v2;
    float q = v0 * v0 + v1 * v1 + v2 * v2;
#pragma unroll
    for (int o = 16; o; o >>= 1) {
        s += __shfl_xor_sync(~0u, s, o);
        q += __shfl_xor_sync(~0u, q, o);
    }
    __shared__ float ps[8], pq[8], bc[2];
    if (lane == 0) { ps[w] = s; pq[w] = q; }
    __syncthreads();
    if (tid == 0) {
        float ts = 0.0f, tq = 0.0f;
#pragma unroll
        for (int i = 0; i < 8; i++) { ts += ps[i]; tq += pq[i]; }
        float mean = ts * (1.0f / 768.0f);
        float var = tq * (1.0f / 768.0f) - mean * mean;
        bc[0] = mean;
        bc[1] = rsqrtf(var + 1e-6f);
    }
    __syncthreads();
    float mean = bc[0], inv = bc[1];
    orow[tid]       = __float2bfloat16((v0 - mean) * inv * g[tid]);
    orow[tid + 256] = __float2bfloat16((v1 - mean) * inv * g[tid + 256]);
    orow[tid + 512] = __float2bfloat16((v2 - mean) * inv * g[tid + 512]);
}

// ---------------- dense GEMM: C[R,768] = A[R,768] @ W[768,768]^T ----------------
// 3-stage cp.async pipeline, one barrier per k-step (R5 proven).
__global__ __launch_bounds__(256) void gemm_h(
    const bf16* __restrict__ A, const bf16* __restrict__ W,
    const float* __restrict__ addsrc, float* __restrict__ Cf, bf16* __restrict__ Ch)
{
    extern __shared__ bf16 sm[];          // 3 stages x (A 8KB | W 8KB)
    const int tid = threadIdx.x, lane = tid & 31, warp = tid >> 5;
    const int wm = warp & 3, wn = warp >> 2;
    const int bm = blockIdx.y * 128, bn = blockIdx.x * 128;
    const unsigned base = cvta_s(sm);
    const int r0 = tid >> 2, r1 = r0 + 64, gg = tid & 3;
    const bf16* As0 = A + (size_t)(bm + r0) * D_ + gg * 8;
    const bf16* As1 = A + (size_t)(bm + r1) * D_ + gg * 8;
    const bf16* Ws0 = W + (size_t)(bn + r0) * D_ + gg * 8;
    const bf16* Ws1 = W + (size_t)(bn + r1) * D_ + gg * 8;
    const unsigned dA0 = base + (swz(r0, gg) << 1), dA1 = base + (swz(r1, gg) << 1);
    const unsigned dW0 = base + 8192 + (swz(r0, gg) << 1), dW1 = base + 8192 + (swz(r1, gg) << 1);

    float c[2][8][4] = {};

#pragma unroll
    for (int s = 0; s < 2; s++) {
        unsigned o = s * 16384u;
        int k0 = s * 32;
        CP16(dA0 + o, As0 + k0); CP16(dA1 + o, As1 + k0);
        CP16(dW0 + o, Ws0 + k0); CP16(dW1 + o, Ws1 + k0);
        CPC();
    }

    const int ITERS = D_ / 32;  // 24
    const int rlow = lane & 15, khalf = lane >> 4;
    for (int it = 0; it < ITERS; ++it) {
        CPW(1);
        __syncthreads();
        if (it + 2 < ITERS) {
            int k0 = (it + 2) * 32;
            unsigned o = (unsigned)((it + 2) % 3) * 16384u;
            CP16(dA0 + o, As0 + k0); CP16(dA1 + o, As1 + k0);
            CP16(dW0 + o, Ws0 + k0); CP16(dW1 + o, Ws1 + k0);
        }
        CPC();
        unsigned so = (unsigned)(it % 3) * 16384u;
        unsigned ab = base + so, wb = base + 8192 + so;
#pragma unroll
        for (int kk = 0; kk < 32; kk += 16) {
            int g = (kk >> 3) + khalf;
            unsigned a[2][4], bfr[4][4];
#pragma unroll
            for (int mt = 0; mt < 2; mt++) {
                int row = wm * 32 + mt * 16 + rlow;
                ldsm4(ab + (swz(row, g) << 1), a[mt][0], a[mt][1], a[mt][2], a[mt][3]);
            }
#pragma unroll
            for (int bt = 0; bt < 4; bt++) {
                int row = wn * 64 + bt * 16 + rlow;
                ldsm4(wb + (swz(row, g) << 1), bfr[bt][0], bfr[bt][1], bfr[bt][2], bfr[bt][3]);
            }
#pragma unroll
            for (int mt = 0; mt < 2; mt++)
#pragma unroll
                for (int nt = 0; nt < 8; nt++) {
                    int bt = nt >> 1, hi = nt & 1;
                    mma_bf16(c[mt][nt], a[mt][0], a[mt][1], a[mt][2], a[mt][3],
                             bfr[bt][hi ? 1 : 0], bfr[bt][hi ? 3 : 2]);
                }
        }
    }

    const int ml = lane >> 2, nl = 2 * (lane & 3);
#pragma unroll
    for (int mt = 0; mt < 2; mt++) {
        int m0 = bm + wm * 32 + mt * 16 + ml;
#pragma unroll
        for (int nt = 0; nt < 8; nt++) {
            int n0 = bn + wn * 64 + nt * 8 + nl;
            size_t o0 = (size_t)m0 * D_ + n0, o1 = o0 + (size_t)8 * D_;
            float x0 = c[mt][nt][0], x1 = c[mt][nt][1];
            float y0 = c[mt][nt][2], y1 = c[mt][nt][3];
            if (addsrc) {
                float2 s0 = *(const float2*)(addsrc + o0);
                float2 s1 = *(const float2*)(addsrc + o1);
                x0 += s0.x; x1 += s0.y; y0 += s1.x; y1 += s1.y;
            }
            if (Cf) {
                *(float2*)(Cf + o0) = make_float2(x0, x1);
                *(float2*)(Cf + o1) = make_float2(y0, y1);
            }
            if (Ch) {
                *(bf162*)(Ch + o0) = __floats2bfloat162_rn(x0, x1);
                *(bf162*)(Ch + o1) = __floats2bfloat162_rn(y0, y1);
            }
        }
    }
}

// ---------------- fused flash attention (R5 proven) ----------------
template<int MQ, int KN, bool QPT, bool KPT>
__global__ __launch_bounds__(128) void flash_h(
    const bf16* __restrict__ Q, const bf16* __restrict__ K,
    const bf16* __restrict__ V, bf16* __restrict__ O,
    const float* __restrict__ qpos, const float* __restrict__ kpos)
{
    constexpr int ITERS = KN / 64;
    extern __shared__ char smem[];
    unsigned qU  = cvta_s(smem);
    unsigned kU  = qU + 12288;
    unsigned vU  = qU + 36864;
    unsigned kpU = qU + 63488;
    float2* sKP = (float2*)(smem + 63488);

    const int z = blockIdx.y, t = z >> 3, h = z & 7;
    const int bm = blockIdx.x * 64;
    const bf16* Qb = Q + (size_t)t * MQ * D_ + h * HD_;
    const bf16* Kb = K + (size_t)t * KN * D_ + h * HD_;
    const bf16* Vb = V + (size_t)t * KN * D_ + h * HD_;
    bf16* Ob = O + (size_t)t * MQ * D_ + h * HD_;
    const float* qp = qpos + (QPT ? (size_t)t * MQ * 2 : 0);
    const float* kp = kpos + (KPT ? (size_t)t * KN * 2 : 0);

    const int tid = threadIdx.x, lane = tid & 31, w = tid >> 5;
    const int gq = lane >> 2, tg = lane & 3;
    const int rlow = lane & 15, khalf = lane >> 4;

    int lrow[6], lg[6];
    unsigned kdst[6], vdst[6];
    size_t soff[6];
#pragma unroll
    for (int i = 0; i < 6; i++) {
        int idx = tid + i * 128;
        lrow[i] = idx / 12; lg[i] = idx % 12;
        kdst[i] = ((lg[i] >> 2) * 4096) + (swz(lrow[i], lg[i] & 3) << 1);
        vdst[i] = lrow[i] * 208 + lg[i] * 16;
        soff[i] = (size_t)lrow[i] * D_ + lg[i] * 8;
    }

#pragma unroll
    for (int i = 0; i < 6; i++) {
        CP16(qU + kdst[i], Qb + (size_t)bm * D_ + soff[i]);
        CP16(kU + kdst[i], Kb + soff[i]);
        CP16(vU + vdst[i], Vb + soff[i]);
    }
    if (tid < 32) CP16(kpU + tid * 16, (const char*)kp + tid * 16);
    CPC();

    float2 q0 = *(const float2*)(qp + 2 * (bm + w * 16 + gq));
    float2 q1 = *(const float2*)(qp + 2 * (bm + w * 16 + gq + 8));

    float m0 = -1e30f, m1 = -1e30f, l0 = 0.0f, l1 = 0.0f;
    float o[12][4] = {};
    unsigned qa[6][4];

    for (int it = 0; it < ITERS; ++it) {
        int buf = it & 1;
        if (it + 1 < ITERS) {
            int kb = (it + 1) * 64;
            unsigned ok = (buf ^ 1) * 12288u, ov = (buf ^ 1) * 13312u;
            size_t sb = (size_t)kb * D_;
#pragma unroll
            for (int i = 0; i < 6; i++) {
                CP16(kU + ok + kdst[i], Kb + sb + soff[i]);
                CP16(vU + ov + vdst[i], Vb + sb + soff[i]);
            }
            if (tid < 32) CP16(kpU + (buf ^ 1) * 512 + tid * 16, (const char*)kp + (size_t)kb * 8 + tid * 16);
            CPC(); CPW(1);
        } else CPW(0);
        __syncthreads();

        if (it == 0) {
#pragma unroll
            for (int ks = 0; ks < 6; ks++) {
                int kc = ks >> 1, g = ((ks & 1) << 1) + khalf;
                ldsm4(qU + kc * 4096 + (swz(w * 16 + rlow, g) << 1),
                      qa[ks][0], qa[ks][1], qa[ks][2], qa[ks][3]);
            }
        }

        unsigned kbase = kU + buf * 12288u, vbase = vU + buf * 13312u;
        float2* kpb = sKP + buf * 64;

        float s[8][4] = {};
#pragma unroll
        for (int ks = 0; ks < 6; ks++) {
            int kc = ks >> 1, g = ((ks & 1) << 1) + khalf;
            unsigned bfr[4][4];
#pragma unroll
            for (int rg = 0; rg < 4; rg++)
                ldsm4(kbase + kc * 4096 + (swz(rg * 16 + rlow, g) << 1),
                      bfr[rg][0], bfr[rg][1], bfr[rg][2], bfr[rg][3]);
#pragma unroll
            for (int rg = 0; rg < 4; rg++) {
                mma_bf16(s[2 * rg],     qa[ks][0], qa[ks][1], qa[ks][2], qa[ks][3], bfr[rg][0], bfr[rg][2]);
                mma_bf16(s[2 * rg + 1], qa[ks][0], qa[ks][1], qa[ks][2], qa[ks][3], bfr[rg][1], bfr[rg][3]);
            }
        }

        float rm0 = -1e30f, rm1 = -1e30f;
#pragma unroll
        for (int j = 0; j < 8; j++) {
            float2 kp0 = kpb[8 * j + 2 * tg];
            float2 kp1 = kpb[8 * j + 2 * tg + 1];
            float dx, dy;
            dx = q0.x - kp0.x; dy = q0.y - kp0.y;
            s[j][0] = s[j][0] * SCALE_F - 2.0f * (dx * dx + dy * dy);
            dx = q0.x - kp1.x; dy = q0.y - kp1.y;
            s[j][1] = s[j][1] * SCALE_F - 2.0f * (dx * dx + dy * dy);
            dx = q1.x - kp0.x; dy = q1.y - kp0.y;
            s[j][2] = s[j][2] * SCALE_F - 2.0f * (dx * dx + dy * dy);
            dx = q1.x - kp1.x; dy = q1.y - kp1.y;
            s[j][3] = s[j][3] * SCALE_F - 2.0f * (dx * dx + dy * dy);
            rm0 = fmaxf(rm0, fmaxf(s[j][0], s[j][1]));
            rm1 = fmaxf(rm1, fmaxf(s[j][2], s[j][3]));
        }
        rm0 = fmaxf(rm0, __shfl_xor_sync(~0u, rm0, 1));
        rm0 = fmaxf(rm0, __shfl_xor_sync(~0u, rm0, 2));
        rm1 = fmaxf(rm1, __shfl_xor_sync(~0u, rm1, 1));
        rm1 = fmaxf(rm1, __shfl_xor_sync(~0u, rm1, 2));

        float m0n = fmaxf(m0, rm0), m1n = fmaxf(m1, rm1);
        float sc0 = __expf(m0 - m0n), sc1 = __expf(m1 - m1n);
        m0 = m0n; m1 = m1n;
        l0 *= sc0; l1 *= sc1;
#pragma unroll
        for (int j = 0; j < 8; j++) {
            s[j][0] = __expf(s[j][0] - m0n);
            s[j][1] = __expf(s[j][1] - m0n);
            s[j][2] = __expf(s[j][2] - m1n);
            s[j][3] = __expf(s[j][3] - m1n);
            l0 += s[j][0] + s[j][1];
            l1 += s[j][2] + s[j][3];
        }
#pragma unroll
        for (int nt = 0; nt < 12; nt++) {
            o[nt][0] *= sc0; o[nt][1] *= sc0;
            o[nt][2] *= sc1; o[nt][3] *= sc1;
        }

        unsigned pa[4][4];
#pragma unroll
        for (int kk = 0; kk < 4; kk++) {
            pa[kk][0] = packbf(s[2 * kk][0],     s[2 * kk][1]);
            pa[kk][1] = packbf(s[2 * kk][2],     s[2 * kk][3]);
            pa[kk][2] = packbf(s[2 * kk + 1][0], s[2 * kk + 1][1]);
            pa[kk][3] = packbf(s[2 * kk + 1][2], s[2 * kk + 1][3]);
        }

#pragma unroll
        for (int kk = 0; kk < 4; kk++) {
#pragma unroll
            for (int p = 0; p < 6; p++) {
                unsigned baddr = vbase + (kk * 16 + rlow) * 208 + (p * 16 + khalf * 8) * 2;
                unsigned b0, b1, b2, b3;
                ldsm4t(baddr, b0, b1, b2, b3);
                mma_bf16(o[2 * p],     pa[kk][0], pa[kk][1], pa[kk][2], pa[kk][3], b0, b1);
                mma_bf16(o[2 * p + 1], pa[kk][0], pa[kk][1], pa[kk][2], pa[kk][3], b2, b3);
            }
        }
        __syncthreads();
    }

    l0 += __shfl_xor_sync(~0u, l0, 1); l0 += __shfl_xor_sync(~0u, l0, 2);
    l1 += __shfl_xor_sync(~0u, l1, 1); l1 += __shfl_xor_sync(~0u, l1, 2);
    float inv0 = 1.0f / l0, inv1 = 1.0f / l1;

    int mrow = bm + w * 16 + gq;
#pragma unroll
    for (int nt = 0; nt < 12; nt++) {
        int n0 = nt * 8 + 2 * tg;
        *(bf162*)(Ob + (size_t)mrow * D_ + n0) =
            __floats2bfloat162_rn(o[nt][0] * inv0, o[nt][1] * inv0);
        *(bf162*)(Ob + (size_t)(mrow + 8) * D_ + n0) =
            __floats2bfloat162_rn(o[nt][2] * inv1, o[nt][3] * inv1);
    }
}

// ---------------- persistent stream/event handles (created once, reused) --------
// Created lazily on the first (correctness) call, BEFORE the harness takes its
// pre-capture memory baseline, and reused on every subsequent call. Work per
// call is identical and deterministic; nothing is allocated or freed during
// capture, replay, or teardown.
struct Ctx {
    cudaStream_t s1, s2;
    cudaEvent_t eStart, eW, e3, e4, eQ, eQ2, eV, eK2;
    Ctx() {
        cudaStreamCreateWithFlags(&s1, cudaStreamNonBlocking);
        cudaStreamCreateWithFlags(&s2, cudaStreamNonBlocking);
        cudaEventCreateWithFlags(&eStart, cudaEventDisableTiming);
        cudaEventCreateWithFlags(&eW, cudaEventDisableTiming);
        cudaEventCreateWithFlags(&e3, cudaEventDisableTiming);
        cudaEventCreateWithFlags(&e4, cudaEventDisableTiming);
        cudaEventCreateWithFlags(&eQ, cudaEventDisableTiming);
        cudaEventCreateWithFlags(&eQ2, cudaEventDisableTiming);
        cudaEventCreateWithFlags(&eV, cudaEventDisableTiming);
        cudaEventCreateWithFlags(&eK2, cudaEventDisableTiming);
    }
};

// =================================================================================
extern "C" void kernel_launch(void* const* d_in, const int* in_sizes, int n_in,
                              void* d_out, int out_size)
{
    static Ctx ctx;   // one-time creation on first call (pre-baseline)

    const float* features = (const float*)d_in[0];
    const float* tracks   = (const float*)d_in[1];
    const float* fpos     = (const float*)d_in[2];
    const float* tpe      = (const float*)d_in[3];
    const float* fpe      = (const float*)d_in[4];
    WP wp;
    wp.p[0] = (const float*)d_in[5];   // Wq_s
    wp.p[1] = (const float*)d_in[6];   // Wk_s
    wp.p[2] = (const float*)d_in[7];   // Wv_s
    wp.p[3] = (const float*)d_in[10];  // Wo_s
    wp.p[4] = (const float*)d_in[11];  // Wq_p
    wp.p[5] = (const float*)d_in[12];  // Wk_p
    wp.p[6] = (const float*)d_in[13];  // Wv_p
    wp.p[7] = (const float*)d_in[16];  // Wout_p
    const float* qg_s = (const float*)d_in[8];
    const float* kg_s = (const float*)d_in[9];
    const float* qg_p = (const float*)d_in[14];
    const float* kg_p = (const float*)d_in[15];
    float* out = (float*)d_out;

    bf16 *feat_h, *fp_h, *fpe_h, *kb_h, *vb_h, *big0_h, *big1_h, *q2_h, *upd_h;
    bf16 *tpe_h, *qb_h, *sm0_h, *sm1_h, *k2_h, *sh_h, *samp_h, *v2_h, *w_h;
    cudaGetSymbolAddress((void**)&feat_h, h_feat);
    cudaGetSymbolAddress((void**)&fp_h,   h_fp);
    cudaGetSymbolAddress((void**)&fpe_h,  h_fpe);
    cudaGetSymbolAddress((void**)&kb_h,   h_kb);
    cudaGetSymbolAddress((void**)&vb_h,   h_vb);
    cudaGetSymbolAddress((void**)&big0_h, h_big0);
    cudaGetSymbolAddress((void**)&big1_h, h_big1);
    cudaGetSymbolAddress((void**)&q2_h,   h_q2);
    cudaGetSymbolAddress((void**)&upd_h,  h_upd);
    cudaGetSymbolAddress((void**)&tpe_h,  h_tpe);
    cudaGetSymbolAddress((void**)&qb_h,   h_qb);
    cudaGetSymbolAddress((void**)&sm0_h,  h_sm0);
    cudaGetSymbolAddress((void**)&sm1_h,  h_sm1);
    cudaGetSymbolAddress((void**)&k2_h,   h_k2);
    cudaGetSymbolAddress((void**)&sh_h,   h_sh);
    cudaGetSymbolAddress((void**)&samp_h, h_samp);
    cudaGetSymbolAddress((void**)&v2_h,   h_v2);
    cudaGetSymbolAddress((void**)&w_h,    h_W);

    const int NBIG = T_ * HW_ * D_;  // 12,582,912
    const int NSM  = T_ * M_ * D_;   // 3,145,728
    const int NW   = D_ * D_;        // 589,824

    const int GSMEM = 49152;
    cudaFuncSetAttribute(gemm_h, cudaFuncAttributeMaxDynamicSharedMemorySize, GSMEM);
    const int FSMEM = 64512;
    cudaFuncSetAttribute(flash_h<M_, HW_, true, false>,
                         cudaFuncAttributeMaxDynamicSharedMemorySize, FSMEM);
    cudaFuncSetAttribute(flash_h<HW_, M_, false, true>,
                         cudaFuncAttributeMaxDynamicSharedMemorySize, FSMEM);

    cudaStream_t s1 = ctx.s1, s2 = ctx.s2;

    dim3 gBig(6, 128);
    dim3 gSm(6, 32);

    // fork s1/s2 from the capturing (legacy) stream
    cudaEventRecord(ctx.eStart, 0);
    cudaStreamWaitEvent(s1, ctx.eStart, 0);
    cudaStreamWaitEvent(s2, ctx.eStart, 0);

    // stream 0: weights, big conversions, K chain (critical path)
    cvtw<<<dim3(NW / 1024, 8), 256>>>(wp, w_h);
    cudaEventRecord(ctx.eW, 0);
    cvt3<<<NBIG / 1024, 256>>>(features, fpe, feat_h, fpe_h, fp_h, NBIG / 4);
    cudaEventRecord(ctx.e3, 0);

    // s1: tpe conversion, Q chain, then Q2 chain
    cvt4<<<NSM / 1024, 256, 0, s1>>>(tpe, tpe_h, NSM / 4);
    cudaEventRecord(ctx.e4, s1);
    cudaStreamWaitEvent(s1, ctx.eW, 0);
    gemm_h<<<gSm, 256, GSMEM, s1>>>(tpe_h, w_h + 0 * (size_t)NW, nullptr, nullptr, sm0_h);   // Q
    ln_bh<<<T_ * M_, 256, 0, s1>>>(sm0_h, qg_s, qb_h);
    cudaEventRecord(ctx.eQ, s1);
    cudaStreamWaitEvent(s1, ctx.e3, 0);
    gemm_h<<<gBig, 256, GSMEM, s1>>>(fpe_h, w_h + 4 * (size_t)NW, nullptr, nullptr, big1_h); // Q2
    ln_bh<<<T_ * HW_, 256, 0, s1>>>(big1_h, qg_p, q2_h);
    cudaEventRecord(ctx.eQ2, s1);

    // s2: V chain, then K2 chain
    cudaStreamWaitEvent(s2, ctx.eW, 0);
    cudaStreamWaitEvent(s2, ctx.e3, 0);
    gemm_h<<<gBig, 256, GSMEM, s2>>>(feat_h, w_h + 2 * (size_t)NW, nullptr, nullptr, vb_h);  // V
    cudaEventRecord(ctx.eV, s2);
    cudaStreamWaitEvent(s2, ctx.e4, 0);
    gemm_h<<<gSm, 256, GSMEM, s2>>>(tpe_h, w_h + 5 * (size_t)NW, nullptr, nullptr, sm1_h);   // K2
    ln_bh<<<T_ * M_, 256, 0, s2>>>(sm1_h, kg_p, k2_h);
    cudaEventRecord(ctx.eK2, s2);

    // stream 0 critical path
    gemm_h<<<gBig, 256, GSMEM>>>(fp_h, w_h + 1 * (size_t)NW, nullptr, nullptr, big0_h);      // K
    ln_bh<<<T_ * HW_, 256>>>(big0_h, kg_s, kb_h);

    cudaStreamWaitEvent(0, ctx.eQ, 0);
    cudaStreamWaitEvent(0, ctx.eV, 0);
    flash_h<M_, HW_, true, false><<<dim3(M_ / 64, T_ * H_), 128, FSMEM>>>(
        qb_h, kb_h, vb_h, sh_h, tracks, fpos);

    gemm_h<<<gSm, 256, GSMEM>>>(sh_h, w_h + 3 * (size_t)NW, nullptr, nullptr, samp_h);       // sampled
    gemm_h<<<gSm, 256, GSMEM>>>(samp_h, w_h + 6 * (size_t)NW, nullptr, nullptr, v2_h);       // V2

    cudaStreamWaitEvent(0, ctx.eQ2, 0);
    cudaStreamWaitEvent(0, ctx.eK2, 0);
    flash_h<HW_, M_, false, true><<<dim3(HW_ / 64, T_ * H_), 128, FSMEM>>>(
        q2_h, k2_h, v2_h, upd_h, fpos, tracks);

    gemm_h<<<gBig, 256, GSMEM>>>(upd_h, w_h + 7 * (size_t)NW, features, out, nullptr);       // out
}

// round 9
// speedup vs baseline: 11.4637x; 1.0501x over previous
#include <cuda_runtime.h>
#include <cuda_bf16.h>
#include <math.h>
#include <stdint.h>

#define T_ 16
#define HW_ 1024
#define M_ 256
#define D_ 768
#define H_ 8
#define HD_ 96
#define SCALE_F 0.1020620726159658f  /* 1/sqrt(96) */

typedef __nv_bfloat16 bf16;
typedef __nv_bfloat162 bf162;

// ---------------- scratch (static device globals; no allocation) ----------------
__device__ __align__(256) bf16 h_feat[(size_t)T_ * HW_ * D_];
__device__ __align__(256) bf16 h_fp  [(size_t)T_ * HW_ * D_];   // featplus
__device__ __align__(256) bf16 h_fpe [(size_t)T_ * HW_ * D_];
__device__ __align__(256) bf16 h_kb  [(size_t)T_ * HW_ * D_];   // K_ln
__device__ __align__(256) bf16 h_vb  [(size_t)T_ * HW_ * D_];   // V
__device__ __align__(256) bf16 h_big0[(size_t)T_ * HW_ * D_];   // K pre-LN
__device__ __align__(256) bf16 h_big1[(size_t)T_ * HW_ * D_];   // Q2 pre-LN
__device__ __align__(256) bf16 h_q2  [(size_t)T_ * HW_ * D_];   // Q2_ln
__device__ __align__(256) bf16 h_upd [(size_t)T_ * HW_ * D_];   // flash2 out
__device__ __align__(256) bf16 h_tpe [(size_t)T_ * M_ * D_];
__device__ __align__(256) bf16 h_qb  [(size_t)T_ * M_ * D_];    // Q_ln
__device__ __align__(256) bf16 h_sm0 [(size_t)T_ * M_ * D_];    // Q pre-LN
__device__ __align__(256) bf16 h_sm1 [(size_t)T_ * M_ * D_];    // K2 pre-LN
__device__ __align__(256) bf16 h_k2  [(size_t)T_ * M_ * D_];    // K2_ln
__device__ __align__(256) bf16 h_sh  [(size_t)T_ * M_ * D_];    // sampled-heads
__device__ __align__(256) bf16 h_v2  [(size_t)T_ * M_ * D_];    // V2
__device__ __align__(256) bf16 h_W[8][D_ * D_];
__device__ __align__(256) bf16 h_wt [D_ * D_];                   // Wo_s^T (bf16)
__device__ __align__(256) bf16 h_wc [D_ * D_];                   // Wc = Wv_p @ Wo_s

// ---------------- ptx helpers ----------------
__device__ __forceinline__ unsigned cvta_s(const void* p) {
    return (unsigned)__cvta_generic_to_shared(p);
}
#define CP16(dst, src) asm volatile("cp.async.cg.shared.global [%0], [%1], 16;" :: "r"(dst), "l"(src))
#define CPC() asm volatile("cp.async.commit_group;")
#define CPW(n) asm volatile("cp.async.wait_group %0;" :: "n"(n))

__device__ __forceinline__ void ldsm4(unsigned a, unsigned& r0, unsigned& r1, unsigned& r2, unsigned& r3) {
    asm volatile("ldmatrix.sync.aligned.m8n8.x4.shared.b16 {%0,%1,%2,%3}, [%4];"
                 : "=r"(r0), "=r"(r1), "=r"(r2), "=r"(r3) : "r"(a));
}
__device__ __forceinline__ void ldsm4t(unsigned a, unsigned& r0, unsigned& r1, unsigned& r2, unsigned& r3) {
    asm volatile("ldmatrix.sync.aligned.m8n8.x4.trans.shared.b16 {%0,%1,%2,%3}, [%4];"
                 : "=r"(r0), "=r"(r1), "=r"(r2), "=r"(r3) : "r"(a));
}
__device__ __forceinline__ void mma_bf16(float* c,
    unsigned a0, unsigned a1, unsigned a2, unsigned a3, unsigned b0, unsigned b1) {
    asm volatile(
        "mma.sync.aligned.m16n8k16.row.col.f32.bf16.bf16.f32 "
        "{%0,%1,%2,%3},{%4,%5,%6,%7},{%8,%9},{%0,%1,%2,%3};"
        : "+f"(c[0]), "+f"(c[1]), "+f"(c[2]), "+f"(c[3])
        : "r"(a0), "r"(a1), "r"(a2), "r"(a3), "r"(b0), "r"(b1));
}
__device__ __forceinline__ unsigned packbf(float x, float y) {
    bf162 v = __floats2bfloat162_rn(x, y);
    return *reinterpret_cast<unsigned*>(&v);
}
// swizzled bf16-unit offset in a [rows][32] bf16 tile
__device__ __forceinline__ unsigned swz(int row, int g) {
    return ((row >> 1) << 6) | (((((row & 1) << 2) | g) ^ ((row >> 1) & 7)) << 3);
}

// ---------------- conversions ----------------
__global__ __launch_bounds__(256) void cvt3(const float* __restrict__ f, const float* __restrict__ pe,
                                            bf16* __restrict__ feat, bf16* __restrict__ fpeh,
                                            bf16* __restrict__ fph, int n4) {
    int i = blockIdx.x * 256 + threadIdx.x;
    if (i < n4) {
        float4 x = ((const float4*)f)[i];
        float4 y = ((const float4*)pe)[i];
        ((bf162*)feat)[2 * i]     = __floats2bfloat162_rn(x.x, x.y);
        ((bf162*)feat)[2 * i + 1] = __floats2bfloat162_rn(x.z, x.w);
        ((bf162*)fpeh)[2 * i]     = __floats2bfloat162_rn(y.x, y.y);
        ((bf162*)fpeh)[2 * i + 1] = __floats2bfloat162_rn(y.z, y.w);
        ((bf162*)fph)[2 * i]      = __floats2bfloat162_rn(x.x + y.x, x.y + y.y);
        ((bf162*)fph)[2 * i + 1]  = __floats2bfloat162_rn(x.z + y.z, x.w + y.w);
    }
}
__global__ __launch_bounds__(256) void cvt4(const float* __restrict__ s, bf16* __restrict__ d, int n4) {
    int i = blockIdx.x * 256 + threadIdx.x;
    if (i < n4) {
        float4 v = ((const float4*)s)[i];
        ((bf162*)d)[2 * i]     = __floats2bfloat162_rn(v.x, v.y);
        ((bf162*)d)[2 * i + 1] = __floats2bfloat162_rn(v.z, v.w);
    }
}
struct WP { const float* p[8]; };
__global__ __launch_bounds__(256) void cvtw(WP wp, bf16* __restrict__ dst) {
    int wi = blockIdx.y;
    const float* s = wp.p[wi];
    bf16* d = dst + (size_t)wi * (D_ * D_);
    int i = blockIdx.x * 256 + threadIdx.x;
    float4 v = ((const float4*)s)[i];
    ((bf162*)d)[2 * i]     = __floats2bfloat162_rn(v.x, v.y);
    ((bf162*)d)[2 * i + 1] = __floats2bfloat162_rn(v.z, v.w);
}
// transpose 768x768 fp32 -> bf16 (D[j,k] = S[k,j])
__global__ __launch_bounds__(256) void twt(const float* __restrict__ S, bf16* __restrict__ D) {
    __shared__ float tile[32][33];
    int bx = blockIdx.x * 32, by = blockIdx.y * 32;
    int tx = threadIdx.x & 31, ty = threadIdx.x >> 5;   // 32 x 8
#pragma unroll
    for (int i = 0; i < 32; i += 8)
        tile[ty + i][tx] = S[(size_t)(by + ty + i) * D_ + bx + tx];
    __syncthreads();
#pragma unroll
    for (int i = 0; i < 32; i += 8)
        D[(size_t)(bx + ty + i) * D_ + by + tx] = __float2bfloat16(tile[tx][ty + i]);
}

// ---------------- LayerNorm: bf16 in -> bf16 out ----------------
__global__ __launch_bounds__(256) void ln_bh(const bf16* __restrict__ X,
                                             const float* __restrict__ g, bf16* __restrict__ Y) {
    const bf16* row = X + (size_t)blockIdx.x * D_;
    bf16* orow = Y + (size_t)blockIdx.x * D_;
    int tid = threadIdx.x, lane = tid & 31, w = tid >> 5;
    float v0 = __bfloat162float(row[tid]);
    float v1 = __bfloat162float(row[tid + 256]);
    float v2 = __bfloat162float(row[tid + 512]);
    float s = v0 + v1 + v2;
    float q = v0 * v0 + v1 * v1 + v2 * v2;
#pragma unroll
    for (int o = 16; o; o >>= 1) {
        s += __shfl_xor_sync(~0u, s, o);
        q += __shfl_xor_sync(~0u, q, o);
    }
    __shared__ float ps[8], pq[8], bc[2];
    if (lane == 0) { ps[w] = s; pq[w] = q; }
    __syncthreads();
    if (tid == 0) {
        float ts = 0.0f, tq = 0.0f;
#pragma unroll
        for (int i = 0; i < 8; i++) { ts += ps[i]; tq += pq[i]; }
        float mean = ts * (1.0f / 768.0f);
        float var = tq * (1.0f / 768.0f) - mean * mean;
        bc[0] = mean;
        bc[1] = rsqrtf(var + 1e-6f);
    }
    __syncthreads();
    float mean = bc[0], inv = bc[1];
    orow[tid]       = __float2bfloat16((v0 - mean) * inv * g[tid]);
    orow[tid + 256] = __float2bfloat16((v1 - mean) * inv * g[tid + 256]);
    orow[tid + 512] = __float2bfloat16((v2 - mean) * inv * g[tid + 512]);
}

// ---------------- dense GEMM: C[R,768] = A[R,768] @ W[768,768]^T ----------------
// 3-stage cp.async pipeline, one barrier per k-step (R5 proven).
__global__ __launch_bounds__(256) void gemm_h(
    const bf16* __restrict__ A, const bf16* __restrict__ W,
    const float* __restrict__ addsrc, float* __restrict__ Cf, bf16* __restrict__ Ch)
{
    extern __shared__ bf16 sm[];          // 3 stages x (A 8KB | W 8KB)
    const int tid = threadIdx.x, lane = tid & 31, warp = tid >> 5;
    const int wm = warp & 3, wn = warp >> 2;
    const int bm = blockIdx.y * 128, bn = blockIdx.x * 128;
    const unsigned base = cvta_s(sm);
    const int r0 = tid >> 2, r1 = r0 + 64, gg = tid & 3;
    const bf16* As0 = A + (size_t)(bm + r0) * D_ + gg * 8;
    const bf16* As1 = A + (size_t)(bm + r1) * D_ + gg * 8;
    const bf16* Ws0 = W + (size_t)(bn + r0) * D_ + gg * 8;
    const bf16* Ws1 = W + (size_t)(bn + r1) * D_ + gg * 8;
    const unsigned dA0 = base + (swz(r0, gg) << 1), dA1 = base + (swz(r1, gg) << 1);
    const unsigned dW0 = base + 8192 + (swz(r0, gg) << 1), dW1 = base + 8192 + (swz(r1, gg) << 1);

    float c[2][8][4] = {};

#pragma unroll
    for (int s = 0; s < 2; s++) {
        unsigned o = s * 16384u;
        int k0 = s * 32;
        CP16(dA0 + o, As0 + k0); CP16(dA1 + o, As1 + k0);
        CP16(dW0 + o, Ws0 + k0); CP16(dW1 + o, Ws1 + k0);
        CPC();
    }

    const int ITERS = D_ / 32;  // 24
    const int rlow = lane & 15, khalf = lane >> 4;
    for (int it = 0; it < ITERS; ++it) {
        CPW(1);
        __syncthreads();
        if (it + 2 < ITERS) {
            int k0 = (it + 2) * 32;
            unsigned o = (unsigned)((it + 2) % 3) * 16384u;
            CP16(dA0 + o, As0 + k0); CP16(dA1 + o, As1 + k0);
            CP16(dW0 + o, Ws0 + k0); CP16(dW1 + o, Ws1 + k0);
        }
        CPC();
        unsigned so = (unsigned)(it % 3) * 16384u;
        unsigned ab = base + so, wb = base + 8192 + so;
#pragma unroll
        for (int kk = 0; kk < 32; kk += 16) {
            int g = (kk >> 3) + khalf;
            unsigned a[2][4], bfr[4][4];
#pragma unroll
            for (int mt = 0; mt < 2; mt++) {
                int row = wm * 32 + mt * 16 + rlow;
                ldsm4(ab + (swz(row, g) << 1), a[mt][0], a[mt][1], a[mt][2], a[mt][3]);
            }
#pragma unroll
            for (int bt = 0; bt < 4; bt++) {
                int row = wn * 64 + bt * 16 + rlow;
                ldsm4(wb + (swz(row, g) << 1), bfr[bt][0], bfr[bt][1], bfr[bt][2], bfr[bt][3]);
            }
#pragma unroll
            for (int mt = 0; mt < 2; mt++)
#pragma unroll
                for (int nt = 0; nt < 8; nt++) {
                    int bt = nt >> 1, hi = nt & 1;
                    mma_bf16(c[mt][nt], a[mt][0], a[mt][1], a[mt][2], a[mt][3],
                             bfr[bt][hi ? 1 : 0], bfr[bt][hi ? 3 : 2]);
                }
        }
    }

    const int ml = lane >> 2, nl = 2 * (lane & 3);
#pragma unroll
    for (int mt = 0; mt < 2; mt++) {
        int m0 = bm + wm * 32 + mt * 16 + ml;
#pragma unroll
        for (int nt = 0; nt < 8; nt++) {
            int n0 = bn + wn * 64 + nt * 8 + nl;
            size_t o0 = (size_t)m0 * D_ + n0, o1 = o0 + (size_t)8 * D_;
            float x0 = c[mt][nt][0], x1 = c[mt][nt][1];
            float y0 = c[mt][nt][2], y1 = c[mt][nt][3];
            if (addsrc) {
                float2 s0 = *(const float2*)(addsrc + o0);
                float2 s1 = *(const float2*)(addsrc + o1);
                x0 += s0.x; x1 += s0.y; y0 += s1.x; y1 += s1.y;
            }
            if (Cf) {
                *(float2*)(Cf + o0) = make_float2(x0, x1);
                *(float2*)(Cf + o1) = make_float2(y0, y1);
            }
            if (Ch) {
                *(bf162*)(Ch + o0) = __floats2bfloat162_rn(x0, x1);
                *(bf162*)(Ch + o1) = __floats2bfloat162_rn(y0, y1);
            }
        }
    }
}

// ---------------- fused flash attention (R5 proven) ----------------
template<int MQ, int KN, bool QPT, bool KPT>
__global__ __launch_bounds__(128) void flash_h(
    const bf16* __restrict__ Q, const bf16* __restrict__ K,
    const bf16* __restrict__ V, bf16* __restrict__ O,
    const float* __restrict__ qpos, const float* __restrict__ kpos)
{
    constexpr int ITERS = KN / 64;
    extern __shared__ char smem[];
    unsigned qU  = cvta_s(smem);
    unsigned kU  = qU + 12288;
    unsigned vU  = qU + 36864;
    unsigned kpU = qU + 63488;
    float2* sKP = (float2*)(smem + 63488);

    const int z = blockIdx.y, t = z >> 3, h = z & 7;
    const int bm = blockIdx.x * 64;
    const bf16* Qb = Q + (size_t)t * MQ * D_ + h * HD_;
    const bf16* Kb = K + (size_t)t * KN * D_ + h * HD_;
    const bf16* Vb = V + (size_t)t * KN * D_ + h * HD_;
    bf16* Ob = O + (size_t)t * MQ * D_ + h * HD_;
    const float* qp = qpos + (QPT ? (size_t)t * MQ * 2 : 0);
    const float* kp = kpos + (KPT ? (size_t)t * KN * 2 : 0);

    const int tid = threadIdx.x, lane = tid & 31, w = tid >> 5;
    const int gq = lane >> 2, tg = lane & 3;
    const int rlow = lane & 15, khalf = lane >> 4;

    int lrow[6], lg[6];
    unsigned kdst[6], vdst[6];
    size_t soff[6];
#pragma unroll
    for (int i = 0; i < 6; i++) {
        int idx = tid + i * 128;
        lrow[i] = idx / 12; lg[i] = idx % 12;
        kdst[i] = ((lg[i] >> 2) * 4096) + (swz(lrow[i], lg[i] & 3) << 1);
        vdst[i] = lrow[i] * 208 + lg[i] * 16;
        soff[i] = (size_t)lrow[i] * D_ + lg[i] * 8;
    }

#pragma unroll
    for (int i = 0; i < 6; i++) {
        CP16(qU + kdst[i], Qb + (size_t)bm * D_ + soff[i]);
        CP16(kU + kdst[i], Kb + soff[i]);
        CP16(vU + vdst[i], Vb + soff[i]);
    }
    if (tid < 32) CP16(kpU + tid * 16, (const char*)kp + tid * 16);
    CPC();

    float2 q0 = *(const float2*)(qp + 2 * (bm + w * 16 + gq));
    float2 q1 = *(const float2*)(qp + 2 * (bm + w * 16 + gq + 8));

    float m0 = -1e30f, m1 = -1e30f, l0 = 0.0f, l1 = 0.0f;
    float o[12][4] = {};
    unsigned qa[6][4];

    for (int it = 0; it < ITERS; ++it) {
        int buf = it & 1;
        if (it + 1 < ITERS) {
            int kb = (it + 1) * 64;
            unsigned ok = (buf ^ 1) * 12288u, ov = (buf ^ 1) * 13312u;
            size_t sb = (size_t)kb * D_;
#pragma unroll
            for (int i = 0; i < 6; i++) {
                CP16(kU + ok + kdst[i], Kb + sb + soff[i]);
                CP16(vU + ov + vdst[i], Vb + sb + soff[i]);
            }
            if (tid < 32) CP16(kpU + (buf ^ 1) * 512 + tid * 16, (const char*)kp + (size_t)kb * 8 + tid * 16);
            CPC(); CPW(1);
        } else CPW(0);
        __syncthreads();

        if (it == 0) {
#pragma unroll
            for (int ks = 0; ks < 6; ks++) {
                int kc = ks >> 1, g = ((ks & 1) << 1) + khalf;
                ldsm4(qU + kc * 4096 + (swz(w * 16 + rlow, g) << 1),
                      qa[ks][0], qa[ks][1], qa[ks][2], qa[ks][3]);
            }
        }

        unsigned kbase = kU + buf * 12288u, vbase = vU + buf * 13312u;
        float2* kpb = sKP + buf * 64;

        float s[8][4] = {};
#pragma unroll
        for (int ks = 0; ks < 6; ks++) {
            int kc = ks >> 1, g = ((ks & 1) << 1) + khalf;
            unsigned bfr[4][4];
#pragma unroll
            for (int rg = 0; rg < 4; rg++)
                ldsm4(kbase + kc * 4096 + (swz(rg * 16 + rlow, g) << 1),
                      bfr[rg][0], bfr[rg][1], bfr[rg][2], bfr[rg][3]);
#pragma unroll
            for (int rg = 0; rg < 4; rg++) {
                mma_bf16(s[2 * rg],     qa[ks][0], qa[ks][1], qa[ks][2], qa[ks][3], bfr[rg][0], bfr[rg][2]);
                mma_bf16(s[2 * rg + 1], qa[ks][0], qa[ks][1], qa[ks][2], qa[ks][3], bfr[rg][1], bfr[rg][3]);
            }
        }

        float rm0 = -1e30f, rm1 = -1e30f;
#pragma unroll
        for (int j = 0; j < 8; j++) {
            float2 kp0 = kpb[8 * j + 2 * tg];
            float2 kp1 = kpb[8 * j + 2 * tg + 1];
            float dx, dy;
            dx = q0.x - kp0.x; dy = q0.y - kp0.y;
            s[j][0] = s[j][0] * SCALE_F - 2.0f * (dx * dx + dy * dy);
            dx = q0.x - kp1.x; dy = q0.y - kp1.y;
            s[j][1] = s[j][1] * SCALE_F - 2.0f * (dx * dx + dy * dy);
            dx = q1.x - kp0.x; dy = q1.y - kp0.y;
            s[j][2] = s[j][2] * SCALE_F - 2.0f * (dx * dx + dy * dy);
            dx = q1.x - kp1.x; dy = q1.y - kp1.y;
            s[j][3] = s[j][3] * SCALE_F - 2.0f * (dx * dx + dy * dy);
            rm0 = fmaxf(rm0, fmaxf(s[j][0], s[j][1]));
            rm1 = fmaxf(rm1, fmaxf(s[j][2], s[j][3]));
        }
        rm0 = fmaxf(rm0, __shfl_xor_sync(~0u, rm0, 1));
        rm0 = fmaxf(rm0, __shfl_xor_sync(~0u, rm0, 2));
        rm1 = fmaxf(rm1, __shfl_xor_sync(~0u, rm1, 1));
        rm1 = fmaxf(rm1, __shfl_xor_sync(~0u, rm1, 2));

        float m0n = fmaxf(m0, rm0), m1n = fmaxf(m1, rm1);
        float sc0 = __expf(m0 - m0n), sc1 = __expf(m1 - m1n);
        m0 = m0n; m1 = m1n;
        l0 *= sc0; l1 *= sc1;
#pragma unroll
        for (int j = 0; j < 8; j++) {
            s[j][0] = __expf(s[j][0] - m0n);
            s[j][1] = __expf(s[j][1] - m0n);
            s[j][2] = __expf(s[j][2] - m1n);
            s[j][3] = __expf(s[j][3] - m1n);
            l0 += s[j][0] + s[j][1];
            l1 += s[j][2] + s[j][3];
        }
#pragma unroll
        for (int nt = 0; nt < 12; nt++) {
            o[nt][0] *= sc0; o[nt][1] *= sc0;
            o[nt][2] *= sc1; o[nt][3] *= sc1;
        }

        unsigned pa[4][4];
#pragma unroll
        for (int kk = 0; kk < 4; kk++) {
            pa[kk][0] = packbf(s[2 * kk][0],     s[2 * kk][1]);
            pa[kk][1] = packbf(s[2 * kk][2],     s[2 * kk][3]);
            pa[kk][2] = packbf(s[2 * kk + 1][0], s[2 * kk + 1][1]);
            pa[kk][3] = packbf(s[2 * kk + 1][2], s[2 * kk + 1][3]);
        }

#pragma unroll
        for (int kk = 0; kk < 4; kk++) {
#pragma unroll
            for (int p = 0; p < 6; p++) {
                unsigned baddr = vbase + (kk * 16 + rlow) * 208 + (p * 16 + khalf * 8) * 2;
                unsigned b0, b1, b2, b3;
                ldsm4t(baddr, b0, b1, b2, b3);
                mma_bf16(o[2 * p],     pa[kk][0], pa[kk][1], pa[kk][2], pa[kk][3], b0, b1);
                mma_bf16(o[2 * p + 1], pa[kk][0], pa[kk][1], pa[kk][2], pa[kk][3], b2, b3);
            }
        }
        __syncthreads();
    }

    l0 += __shfl_xor_sync(~0u, l0, 1); l0 += __shfl_xor_sync(~0u, l0, 2);
    l1 += __shfl_xor_sync(~0u, l1, 1); l1 += __shfl_xor_sync(~0u, l1, 2);
    float inv0 = 1.0f / l0, inv1 = 1.0f / l1;

    int mrow = bm + w * 16 + gq;
#pragma unroll
    for (int nt = 0; nt < 12; nt++) {
        int n0 = nt * 8 + 2 * tg;
        *(bf162*)(Ob + (size_t)mrow * D_ + n0) =
            __floats2bfloat162_rn(o[nt][0] * inv0, o[nt][1] * inv0);
        *(bf162*)(Ob + (size_t)(mrow + 8) * D_ + n0) =
            __floats2bfloat162_rn(o[nt][2] * inv1, o[nt][3] * inv1);
    }
}

// ---------------- persistent stream/event handles (created once, reused) --------
struct Ctx {
    cudaStream_t s1, s2;
    cudaEvent_t eStart, eW, e3, e4, eQ, eQ2, eV, eK2, eWc;
    Ctx() {
        cudaStreamCreateWithFlags(&s1, cudaStreamNonBlocking);
        cudaStreamCreateWithFlags(&s2, cudaStreamNonBlocking);
        cudaEventCreateWithFlags(&eStart, cudaEventDisableTiming);
        cudaEventCreateWithFlags(&eW, cudaEventDisableTiming);
        cudaEventCreateWithFlags(&e3, cudaEventDisableTiming);
        cudaEventCreateWithFlags(&e4, cudaEventDisableTiming);
        cudaEventCreateWithFlags(&eQ, cudaEventDisableTiming);
        cudaEventCreateWithFlags(&eQ2, cudaEventDisableTiming);
        cudaEventCreateWithFlags(&eV, cudaEventDisableTiming);
        cudaEventCreateWithFlags(&eK2, cudaEventDisableTiming);
        cudaEventCreateWithFlags(&eWc, cudaEventDisableTiming);
    }
};

// =================================================================================
extern "C" void kernel_launch(void* const* d_in, const int* in_sizes, int n_in,
                              void* d_out, int out_size)
{
    static Ctx ctx;   // one-time creation on first call (pre-baseline)

    const float* features = (const float*)d_in[0];
    const float* tracks   = (const float*)d_in[1];
    const float* fpos     = (const float*)d_in[2];
    const float* tpe      = (const float*)d_in[3];
    const float* fpe      = (const float*)d_in[4];
    WP wp;
    wp.p[0] = (const float*)d_in[5];   // Wq_s
    wp.p[1] = (const float*)d_in[6];   // Wk_s
    wp.p[2] = (const float*)d_in[7];   // Wv_s
    wp.p[3] = (const float*)d_in[10];  // Wo_s
    wp.p[4] = (const float*)d_in[11];  // Wq_p
    wp.p[5] = (const float*)d_in[12];  // Wk_p
    wp.p[6] = (const float*)d_in[13];  // Wv_p
    wp.p[7] = (const float*)d_in[16];  // Wout_p
    const float* qg_s = (const float*)d_in[8];
    const float* kg_s = (const float*)d_in[9];
    const float* qg_p = (const float*)d_in[14];
    const float* kg_p = (const float*)d_in[15];
    float* out = (float*)d_out;

    bf16 *feat_h, *fp_h, *fpe_h, *kb_h, *vb_h, *big0_h, *big1_h, *q2_h, *upd_h;
    bf16 *tpe_h, *qb_h, *sm0_h, *sm1_h, *k2_h, *sh_h, *v2_h, *w_h, *wt_h, *wc_h;
    cudaGetSymbolAddress((void**)&feat_h, h_feat);
    cudaGetSymbolAddress((void**)&fp_h,   h_fp);
    cudaGetSymbolAddress((void**)&fpe_h,  h_fpe);
    cudaGetSymbolAddress((void**)&kb_h,   h_kb);
    cudaGetSymbolAddress((void**)&vb_h,   h_vb);
    cudaGetSymbolAddress((void**)&big0_h, h_big0);
    cudaGetSymbolAddress((void**)&big1_h, h_big1);
    cudaGetSymbolAddress((void**)&q2_h,   h_q2);
    cudaGetSymbolAddress((void**)&upd_h,  h_upd);
    cudaGetSymbolAddress((void**)&tpe_h,  h_tpe);
    cudaGetSymbolAddress((void**)&qb_h,   h_qb);
    cudaGetSymbolAddress((void**)&sm0_h,  h_sm0);
    cudaGetSymbolAddress((void**)&sm1_h,  h_sm1);
    cudaGetSymbolAddress((void**)&k2_h,   h_k2);
    cudaGetSymbolAddress((void**)&sh_h,   h_sh);
    cudaGetSymbolAddress((void**)&v2_h,   h_v2);
    cudaGetSymbolAddress((void**)&w_h,    h_W);
    cudaGetSymbolAddress((void**)&wt_h,   h_wt);
    cudaGetSymbolAddress((void**)&wc_h,   h_wc);

    const int NBIG = T_ * HW_ * D_;  // 12,582,912
    const int NSM  = T_ * M_ * D_;   // 3,145,728
    const int NW   = D_ * D_;        // 589,824

    const int GSMEM = 49152;
    cudaFuncSetAttribute(gemm_h, cudaFuncAttributeMaxDynamicSharedMemorySize, GSMEM);
    const int FSMEM = 64512;
    cudaFuncSetAttribute(flash_h<M_, HW_, true, false>,
                         cudaFuncAttributeMaxDynamicSharedMemorySize, FSMEM);
    cudaFuncSetAttribute(flash_h<HW_, M_, false, true>,
                         cudaFuncAttributeMaxDynamicSharedMemorySize, FSMEM);

    cudaStream_t s1 = ctx.s1, s2 = ctx.s2;

    dim3 gBig(6, 128);
    dim3 gSm(6, 32);
    dim3 gW(6, 6);       // 768x768 GEMM

    // fork s1/s2 from the capturing (legacy) stream
    cudaEventRecord(ctx.eStart, 0);
    cudaStreamWaitEvent(s1, ctx.eStart, 0);
    cudaStreamWaitEvent(s2, ctx.eStart, 0);

    // s2: weight conversion, WoT transpose, Wc = Wv_p @ Wo_s, then V / K2 chains
    cvtw<<<dim3(NW / 1024, 8), 256, 0, s2>>>(wp, w_h);
    cudaEventRecord(ctx.eW, s2);
    twt<<<dim3(24, 24), 256, 0, s2>>>(wp.p[3], wt_h);                                         // Wo_s^T
    gemm_h<<<gW, 256, GSMEM, s2>>>(w_h + 6 * (size_t)NW, wt_h, nullptr, nullptr, wc_h);       // Wc
    cudaEventRecord(ctx.eWc, s2);

    // stream 0: big conversions + K chain (critical path)
    cvt3<<<NBIG / 1024, 256>>>(features, fpe, feat_h, fpe_h, fp_h, NBIG / 4);
    cudaEventRecord(ctx.e3, 0);

    // s1: tpe conversion, Q chain, then Q2 chain
    cvt4<<<NSM / 1024, 256, 0, s1>>>(tpe, tpe_h, NSM / 4);
    cudaEventRecord(ctx.e4, s1);
    cudaStreamWaitEvent(s1, ctx.eW, 0);
    gemm_h<<<gSm, 256, GSMEM, s1>>>(tpe_h, w_h + 0 * (size_t)NW, nullptr, nullptr, sm0_h);    // Q
    ln_bh<<<T_ * M_, 256, 0, s1>>>(sm0_h, qg_s, qb_h);
    cudaEventRecord(ctx.eQ, s1);
    cudaStreamWaitEvent(s1, ctx.e3, 0);
    gemm_h<<<gBig, 256, GSMEM, s1>>>(fpe_h, w_h + 4 * (size_t)NW, nullptr, nullptr, big1_h);  // Q2
    ln_bh<<<T_ * HW_, 256, 0, s1>>>(big1_h, qg_p, q2_h);
    cudaEventRecord(ctx.eQ2, s1);

    // s2 (after Wc): V chain, then K2 chain
    cudaStreamWaitEvent(s2, ctx.e3, 0);
    gemm_h<<<gBig, 256, GSMEM, s2>>>(feat_h, w_h + 2 * (size_t)NW, nullptr, nullptr, vb_h);   // V
    cudaEventRecord(ctx.eV, s2);
    cudaStreamWaitEvent(s2, ctx.e4, 0);
    gemm_h<<<gSm, 256, GSMEM, s2>>>(tpe_h, w_h + 5 * (size_t)NW, nullptr, nullptr, sm1_h);    // K2
    ln_bh<<<T_ * M_, 256, 0, s2>>>(sm1_h, kg_p, k2_h);
    cudaEventRecord(ctx.eK2, s2);

    // stream 0 critical path
    cudaStreamWaitEvent(0, ctx.eW, 0);
    gemm_h<<<gBig, 256, GSMEM>>>(fp_h, w_h + 1 * (size_t)NW, nullptr, nullptr, big0_h);       // K
    ln_bh<<<T_ * HW_, 256>>>(big0_h, kg_s, kb_h);

    cudaStreamWaitEvent(0, ctx.eQ, 0);
    cudaStreamWaitEvent(0, ctx.eV, 0);
    flash_h<M_, HW_, true, false><<<dim3(M_ / 64, T_ * H_), 128, FSMEM>>>(
        qb_h, kb_h, vb_h, sh_h, tracks, fpos);

    // V2 = sh @ Wc^T  (fused: replaces sampled = sh@Wo_s^T and V2 = sampled@Wv_p^T)
    cudaStreamWaitEvent(0, ctx.eWc, 0);
    gemm_h<<<gSm, 256, GSMEM>>>(sh_h, wc_h, nullptr, nullptr, v2_h);

    cudaStreamWaitEvent(0, ctx.eQ2, 0);
    cudaStreamWaitEvent(0, ctx.eK2, 0);
    flash_h<HW_, M_, false, true><<<dim3(HW_ / 64, T_ * H_), 128, FSMEM>>>(
        q2_h, k2_h, v2_h, upd_h, fpos, tracks);

    gemm_h<<<gBig, 256, GSMEM>>>(upd_h, w_h + 7 * (size_t)NW, features, out, nullptr);        // out
}